// round 14
// baseline (speedup 1.0000x reference)
#include <cuda_runtime.h>
#include <cuda_bf16.h>
#include <math.h>
#include <stdint.h>

#define Bn 4
#define Tn 4096
#define Cn 2048
#define HD 128
#define Mn (Bn*Tn)
#define SCALE 0.022097086912079608f   // 1/sqrt(2048)

// ---------------- device scratch (static, no runtime alloc) ----------------
// g_wf, g_Q, g_K use PAIR-PERMUTED layout within each 8-float group:
//   logical j -> physical (j<4 ? 2j : 2j-7), so (t2, t2+4) sit adjacent.
__device__ float        g_wf[2*(size_t)HD*Cn];        // Wq, Wk (tf32, permuted)
__device__ __nv_bfloat16 g_wh[(size_t)HD*Cn];         // Wv hi
__device__ __nv_bfloat16 g_wl[(size_t)HD*Cn];         // Wv lo
__device__ float        g_Q[(size_t)Mn*HD];           // tf32 fp32, permuted
__device__ float        g_K[(size_t)Mn*HD];           // tf32 fp32, permuted
__device__ __nv_bfloat16 g_Vh[(size_t)Mn*HD], g_Vl[(size_t)Mn*HD];
__device__ int g_ctr;

// ---------------- base-ISA PTX helpers ---------------
__device__ __forceinline__ unsigned smem_u32(const void* p) {
    unsigned a;
    asm("{ .reg .u64 t; cvta.to.shared.u64 t, %1; cvt.u32.u64 %0, t; }" : "=r"(a) : "l"(p));
    return a;
}
#define CP16(dst, src) \
    asm volatile("cp.async.cg.shared.global [%0], [%1], 16;" \
                 :: "r"(dst), "l"(__cvta_generic_to_global((const void*)(src))) : "memory")
#define CP_COMMIT()  asm volatile("cp.async.commit_group;" ::: "memory")
#define CP_WAIT2()   asm volatile("cp.async.wait_group 2;" ::: "memory")
#define CP_WAIT1()   asm volatile("cp.async.wait_group 1;" ::: "memory")
#define CP_WAIT0()   asm volatile("cp.async.wait_group 0;" ::: "memory")

__device__ __forceinline__ void ldsm4(unsigned& r0, unsigned& r1, unsigned& r2, unsigned& r3,
                                      unsigned addr) {
    asm volatile("ldmatrix.sync.aligned.m8n8.x4.shared.b16 {%0,%1,%2,%3}, [%4];"
                 : "=r"(r0), "=r"(r1), "=r"(r2), "=r"(r3) : "r"(addr));
}
__device__ __forceinline__ void ldsm4t(unsigned& r0, unsigned& r1, unsigned& r2, unsigned& r3,
                                       unsigned addr) {
    asm volatile("ldmatrix.sync.aligned.m8n8.x4.trans.shared.b16 {%0,%1,%2,%3}, [%4];"
                 : "=r"(r0), "=r"(r1), "=r"(r2), "=r"(r3) : "r"(addr));
}
__device__ __forceinline__ void mma16816(float* c, const unsigned* a, unsigned b0, unsigned b1) {
    asm volatile(
        "mma.sync.aligned.m16n8k16.row.col.f32.bf16.bf16.f32 "
        "{%0,%1,%2,%3},{%4,%5,%6,%7},{%8,%9},{%0,%1,%2,%3};"
        : "+f"(c[0]), "+f"(c[1]), "+f"(c[2]), "+f"(c[3])
        : "r"(a[0]), "r"(a[1]), "r"(a[2]), "r"(a[3]), "r"(b0), "r"(b1));
}
__device__ __forceinline__ void mma1688t(float* c, const unsigned* a, unsigned b0, unsigned b1) {
    asm volatile(
        "mma.sync.aligned.m16n8k8.row.col.f32.tf32.tf32.f32 "
        "{%0,%1,%2,%3},{%4,%5,%6,%7},{%8,%9},{%0,%1,%2,%3};"
        : "+f"(c[0]), "+f"(c[1]), "+f"(c[2]), "+f"(c[3])
        : "r"(a[0]), "r"(a[1]), "r"(a[2]), "r"(a[3]), "r"(b0), "r"(b1));
}
__device__ __forceinline__ unsigned cvt_tf32(float f) {
    unsigned r; asm("cvt.rna.tf32.f32 %0, %1;" : "=r"(r) : "f"(f)); return r;
}
__device__ __forceinline__ unsigned packbf(float a, float b) {
    __nv_bfloat162 h = __floats2bfloat162_rn(a, b);
    return *(unsigned*)&h;
}
__device__ __forceinline__ void packhl(float a, float b, unsigned& h, unsigned& l) {
    __nv_bfloat162 hh = __floats2bfloat162_rn(a, b);
    unsigned hb = *(unsigned*)&hh;
    float fa = __uint_as_float(hb << 16);
    float fb = __uint_as_float(hb & 0xffff0000u);
    __nv_bfloat162 ll = __floats2bfloat162_rn(a - fa, b - fb);
    h = hb; l = *(unsigned*)&ll;
}

// ---------------------------------------------------------------------------
// weight prep: Wq,Wk -> tf32 fp32 PERMUTED; Wv -> bf16 hi/lo. Zeros counter.
// ---------------------------------------------------------------------------
#define NW4 (HD*Cn/4)          // 65536 float4 per weight

__global__ void wsplit_kernel(const float* __restrict__ Wq, const float* __restrict__ Wk,
                              const float* __restrict__ Wv)
{
    int i = blockIdx.x * blockDim.x + threadIdx.x;
    if (i == 0) g_ctr = 0;
    if (i >= 3 * NW4) return;
    int sel = i >> 16;
    int j   = i & (NW4 - 1);
    if (sel < 2) {
        const float* src = (sel == 0) ? Wq : Wk;
        float4 v = ((const float4*)src)[j];
        // logical elements 4j..4j+3; group = j>>1; half = j&1 (0: j0..3, 1: j4..7)
        // physical: j<4 -> 2j ; j>=4 -> 2j-7  => stride-2 starting at (j&1)
        float* dst = g_wf + (size_t)sel * HD * Cn + (size_t)(j >> 1) * 8 + (j & 1);
        dst[0] = __uint_as_float(cvt_tf32(v.x));
        dst[2] = __uint_as_float(cvt_tf32(v.y));
        dst[4] = __uint_as_float(cvt_tf32(v.z));
        dst[6] = __uint_as_float(cvt_tf32(v.w));
    } else {
        float4 v = ((const float4*)Wv)[j];
        unsigned h0, l0, h1, l1;
        packhl(v.x, v.y, h0, l0);
        packhl(v.z, v.w, h1, l1);
        ((uint2*)g_wh)[j] = make_uint2(h0, h1);
        ((uint2*)g_wl)[j] = make_uint2(l0, l1);
    }
}

// permuted position of logical in-group index j (0..7)
__device__ __forceinline__ int permp(int j) { return (j < 4) ? 2*j : 2*j - 7; }

// ---------------------------------------------------------------------------
// Q/K projection GEMM, single-product tf32, permuted W (B-frag = 1 v2 LDS).
// grid (2, 256); 2 CTAs/SM; 3-stage cp.async pipeline.
// ---------------------------------------------------------------------------
#define QK_A_B   (64*144)
#define QK_W_OFF QK_A_B
#define QK_STAGE (QK_A_B + 128*144)      // 27648
#define QK_SMEM  (3*QK_STAGE)            // 82944

__global__ __launch_bounds__(256, 2) void gemm_qk_kernel(const float* __restrict__ x,
                                                         const float* __restrict__ cs,
                                                         const float* __restrict__ sn)
{
    extern __shared__ char gsm[];
    const int tid  = threadIdx.x;
    const int wid  = tid >> 5;
    const int lane = tid & 31;
    const int g    = lane >> 2;
    const int t2   = lane & 3;
    const int z    = blockIdx.x;                 // 0=Q, 1=K
    const int m0   = blockIdx.y * 64;
    const unsigned sbase = smem_u32(gsm);

    const float* xA = x + (size_t)m0 * Cn;
    const float* Wf = g_wf + (size_t)z * HD * Cn;

    #define QK_LOAD(cc, soff)                                                 \
    {                                                                         \
        int k0 = (cc) * 32;                                                   \
        _Pragma("unroll")                                                     \
        for (int q = 0; q < 2; q++) {                                         \
            int u = tid + q * 256;                                            \
            int row = u >> 3, gg = u & 7;                                     \
            CP16((soff) + sbase + row * 144 + gg * 16,                        \
                 xA + (size_t)row * Cn + k0 + gg * 4);                        \
        }                                                                     \
        _Pragma("unroll")                                                     \
        for (int q = 0; q < 4; q++) {                                         \
            int u = tid + q * 256;                                            \
            int row = u >> 3, gg = u & 7;                                     \
            CP16((soff) + sbase + QK_W_OFF + row * 144 + gg * 16,             \
                 Wf + (size_t)row * Cn + k0 + gg * 4);                        \
        }                                                                     \
        CP_COMMIT();                                                          \
    }

    const int wm = wid & 3;
    const int wn = wid >> 2;
    const int mrow0 = wm * 16;
    const int nrow0 = wn * 64;

    float c[8][4];
    #pragma unroll
    for (int b = 0; b < 8; b++)
        #pragma unroll
        for (int d = 0; d < 4; d++) c[b][d] = 0.f;

    QK_LOAD(0, 0u);
    QK_LOAD(1, (unsigned)QK_STAGE);

    for (int ch = 0; ch < 64; ch++) {
        const unsigned st = (unsigned)((ch % 3) * QK_STAGE);
        if (ch + 2 < 64) { QK_LOAD(ch + 2, (unsigned)(((ch + 2) % 3) * QK_STAGE)); CP_WAIT2(); }
        else if (ch + 1 < 64) { CP_WAIT1(); }
        else { CP_WAIT0(); }
        __syncthreads();

        #pragma unroll
        for (int k8 = 0; k8 < 4; k8++) {
            // A fragment: x fp32 (unpermuted), cvt to tf32 in-register
            unsigned a[4];
            {
                unsigned ab = sbase + st + (unsigned)(mrow0 + g) * 144
                            + (unsigned)k8 * 32 + (unsigned)t2 * 4;
                float f0, f1, f2, f3;
                asm volatile("ld.shared.f32 %0, [%1];" : "=f"(f0) : "r"(ab));
                asm volatile("ld.shared.f32 %0, [%1];" : "=f"(f1) : "r"(ab + 8*144));
                asm volatile("ld.shared.f32 %0, [%1];" : "=f"(f2) : "r"(ab + 16));
                asm volatile("ld.shared.f32 %0, [%1];" : "=f"(f3) : "r"(ab + 8*144 + 16));
                a[0] = cvt_tf32(f0); a[1] = cvt_tf32(f1);
                a[2] = cvt_tf32(f2); a[3] = cvt_tf32(f3);
            }
            #pragma unroll
            for (int np = 0; np < 8; np++) {
                // permuted W: (t2, t2+4) adjacent -> single v2
                unsigned bb = sbase + st + QK_W_OFF
                            + (unsigned)(nrow0 + np * 8 + g) * 144
                            + (unsigned)k8 * 32 + (unsigned)t2 * 8;
                unsigned b0, b1;
                asm volatile("ld.shared.v2.b32 {%0,%1}, [%2];" : "=r"(b0), "=r"(b1) : "r"(bb));
                mma1688t(c[np], a, b0, b1);
            }
        }
        __syncthreads();
    }

    // epilogue: RoPE (+ scale on Q); store tf32 fp32 PERMUTED
    float* Out = (z == 0) ? g_Q : g_K;
    {
        int mA = m0 + mrow0 + g;
        int tA = mA & (Tn - 1);
        const int p0 = permp(2*t2);          // physical pos of logical 2t2
        const int p1 = permp(2*t2 + 1);
        #pragma unroll
        for (int np = 0; np < 8; np++) {
            int colb = nrow0 + np * 8;       // group base
            int j = (colb + 2*t2) >> 1;      // RoPE pair index
            float c0 = cs[tA*64 + j],     s0 = sn[tA*64 + j];
            float c1 = cs[(tA+8)*64 + j], s1 = sn[(tA+8)*64 + j];
            float r0 = c[np][0]*c0 - c[np][1]*s0, i0 = c[np][0]*s0 + c[np][1]*c0;
            float r1 = c[np][2]*c1 - c[np][3]*s1, i1 = c[np][2]*s1 + c[np][3]*c1;
            if (z == 0) { r0 *= SCALE; i0 *= SCALE; r1 *= SCALE; i1 *= SCALE; }
            float* o0 = &Out[(size_t)mA * HD + colb];
            float* o1 = &Out[(size_t)(mA + 8) * HD + colb];
            o0[p0] = __uint_as_float(cvt_tf32(r0));
            o0[p1] = __uint_as_float(cvt_tf32(i0));
            o1[p0] = __uint_as_float(cvt_tf32(r1));
            o1[p1] = __uint_as_float(cvt_tf32(i1));
        }
    }
}

// ---------------------------------------------------------------------------
// V projection GEMM: bf16 3-product (unchanged). grid (1, 256).
// ---------------------------------------------------------------------------
#define A_BYTES  (64*160)
#define BH_OFF   A_BYTES
#define BL_OFF   (A_BYTES + 8192)
#define STAGE_B  (A_BYTES + 16384)
#define V_SMEM   (3*STAGE_B)

__device__ __forceinline__ unsigned ldsm_addr(unsigned tile_base, int row0, int kg0, int lane) {
    int r  = row0 + (lane & 7) + ((lane >> 3) & 1) * 8;
    int kg = kg0 + (lane >> 4);
    return tile_base + r * 64 + (((unsigned)(kg ^ ((r >> 1) & 3))) << 4);
}

__device__ __forceinline__ void lda_frag(unsigned abase, int row0, int ks,
                                         int g, int t2, unsigned* ah, unsigned* al) {
    unsigned a0 = abase + (unsigned)(row0 + g) * 160 + (unsigned)ks * 64 + (unsigned)t2 * 8;
    float2 f01, f23, f45, f67;
    asm volatile("ld.shared.v2.f32 {%0,%1}, [%2];" : "=f"(f01.x), "=f"(f01.y) : "r"(a0));
    asm volatile("ld.shared.v2.f32 {%0,%1}, [%2];" : "=f"(f23.x), "=f"(f23.y) : "r"(a0 + 8*160));
    asm volatile("ld.shared.v2.f32 {%0,%1}, [%2];" : "=f"(f45.x), "=f"(f45.y) : "r"(a0 + 32));
    asm volatile("ld.shared.v2.f32 {%0,%1}, [%2];" : "=f"(f67.x), "=f"(f67.y) : "r"(a0 + 8*160 + 32));
    packhl(f01.x, f01.y, ah[0], al[0]);
    packhl(f23.x, f23.y, ah[1], al[1]);
    packhl(f45.x, f45.y, ah[2], al[2]);
    packhl(f67.x, f67.y, ah[3], al[3]);
}

__global__ __launch_bounds__(256, 2) void gemm_v_kernel(const float* __restrict__ x)
{
    extern __shared__ char gsm[];
    const int tid  = threadIdx.x;
    const int wid  = tid >> 5;
    const int lane = tid & 31;
    const int g    = lane >> 2;
    const int t2   = lane & 3;
    const int m0   = blockIdx.y * 64;
    const unsigned sbase = smem_u32(gsm);

    const float* xA = x + (size_t)m0 * Cn;
    const __nv_bfloat16* Bh = g_wh;
    const __nv_bfloat16* Bl = g_wl;

    #define V_LOAD(cc, soff)                                                      \
    {                                                                             \
        int k0 = (cc) * 32;                                                       \
        _Pragma("unroll")                                                         \
        for (int q = 0; q < 2; q++) {                                             \
            int u = tid + q * 256;                                                \
            int row = u >> 3, gg = u & 7;                                         \
            CP16((soff) + sbase + row * 160 + gg * 16,                            \
                 xA + (size_t)row * Cn + k0 + gg * 4);                            \
        }                                                                         \
        _Pragma("unroll")                                                         \
        for (int q = 0; q < 2; q++) {                                             \
            int row = (tid >> 2) + q * 64;                                        \
            int lg  = tid & 3;                                                    \
            unsigned d = (soff) + row * 64 + (((unsigned)(lg ^ ((row>>1)&3)))<<4);\
            size_t so = (size_t)row * Cn + k0 + lg * 8;                           \
            CP16(sbase + d + BH_OFF, Bh + so);                                    \
            CP16(sbase + d + BL_OFF, Bl + so);                                    \
        }                                                                         \
        CP_COMMIT();                                                              \
    }

    const int wm = wid & 3;
    const int wn = wid >> 2;
    const int mrow0 = wm * 16;
    const int nrow0 = wn * 64;

    float c[8][4];
    #pragma unroll
    for (int b = 0; b < 8; b++)
        #pragma unroll
        for (int d = 0; d < 4; d++) c[b][d] = 0.f;

    V_LOAD(0, 0u);
    V_LOAD(1, (unsigned)STAGE_B);

    for (int ch = 0; ch < 64; ch++) {
        const unsigned st = (unsigned)((ch % 3) * STAGE_B);
        if (ch + 2 < 64) { V_LOAD(ch + 2, (unsigned)(((ch + 2) % 3) * STAGE_B)); CP_WAIT2(); }
        else if (ch + 1 < 64) { CP_WAIT1(); }
        else { CP_WAIT0(); }
        __syncthreads();

        #pragma unroll
        for (int ks = 0; ks < 2; ks++) {
            const int kg0 = ks * 2;
            unsigned ah[4], al[4], bh[4][4], bl[4][4];
            lda_frag(sbase + st, mrow0, ks, g, t2, ah, al);
            #pragma unroll
            for (int np = 0; np < 4; np++) {
                unsigned aB = ldsm_addr(sbase + st + BH_OFF, nrow0 + np*16, kg0, lane);
                unsigned aC = ldsm_addr(sbase + st + BL_OFF, nrow0 + np*16, kg0, lane);
                ldsm4(bh[np][0], bh[np][1], bh[np][2], bh[np][3], aB);
                ldsm4(bl[np][0], bl[np][1], bl[np][2], bl[np][3], aC);
            }
            #pragma unroll
            for (int np = 0; np < 4; np++) {
                mma16816(c[np*2],   ah, bh[np][0], bh[np][2]);
                mma16816(c[np*2],   ah, bl[np][0], bl[np][2]);
                mma16816(c[np*2],   al, bh[np][0], bh[np][2]);
                mma16816(c[np*2+1], ah, bh[np][1], bh[np][3]);
                mma16816(c[np*2+1], ah, bl[np][1], bl[np][3]);
                mma16816(c[np*2+1], al, bh[np][1], bh[np][3]);
            }
        }
        __syncthreads();
    }

    {
        int mA = m0 + mrow0 + g;
        #pragma unroll
        for (int nt = 0; nt < 8; nt++) {
            int col = nrow0 + nt * 8 + t2 * 2;
            unsigned h, l;
            packhl(c[nt][0], c[nt][1], h, l);
            *(unsigned*)&g_Vh[(size_t)mA * HD + col] = h;
            *(unsigned*)&g_Vl[(size_t)mA * HD + col] = l;
            packhl(c[nt][2], c[nt][3], h, l);
            *(unsigned*)&g_Vh[(size_t)(mA + 8) * HD + col] = h;
            *(unsigned*)&g_Vl[(size_t)(mA + 8) * HD + col] = l;
        }
    }
}

// ---------------------------------------------------------------------------
// Flash attention: S via tf32 with Q resident in REGISTERS (loaded once/task)
// and permuted K (B-frag = 1 v2 LDS). P.V bf16 3-product. Pipelined K/V.
// smem: Q 64x528 | K 64x528 | Vh 16K | Vl 16K = 100352B -> 2 CTAs/SM.
// ---------------------------------------------------------------------------
#define FQ  0
#define FK  33792
#define FVH 67584
#define FVL 83968
#define FLASH_SMEM 100352
#define NTASKS (Bn * (Tn/64))    // 256

__device__ __forceinline__ unsigned faddr(unsigned base, int row0, int g0, int lane) {
    int r = row0 + (lane & 7) + ((lane >> 3) & 1) * 8;
    int g = g0 + (lane >> 4);
    return base + r * 256 + (((unsigned)(g ^ (r & 7))) << 4);
}

__global__ __launch_bounds__(128, 2) void flash_kernel(float* __restrict__ out)
{
    extern __shared__ char fsm[];
    __shared__ int t_sh;
    const unsigned sb = smem_u32(fsm);
    const int tid  = threadIdx.x;
    const int wid  = tid >> 5;
    const int lane = tid & 31;
    const int g    = lane >> 2;
    const int t2   = lane & 3;

    #define LOAD_K(b, k0)                                                       \
    {                                                                           \
        _Pragma("unroll")                                                       \
        for (int q = 0; q < 16; q++) {                                          \
            int u = tid + q * 128;                                              \
            int r = u >> 5, gg = u & 31;                                        \
            CP16(sb + FK + r * 528 + gg * 16,                                   \
                 g_K + ((size_t)((b)*Tn + (k0) + r)) * HD + gg * 4);            \
        }                                                                       \
        CP_COMMIT();                                                            \
    }
    #define LOAD_V(b, k0)                                                       \
    {                                                                           \
        _Pragma("unroll")                                                       \
        for (int q = 0; q < 8; q++) {                                           \
            int u = tid + q * 128;                                              \
            int r = u >> 4, gg = u & 15;                                        \
            unsigned d = r * 256 + (((unsigned)(gg ^ (r & 7))) << 4);           \
            size_t ko = ((size_t)((b)*Tn + (k0) + r)) * HD + gg * 8;            \
            CP16(sb + FVH + d, g_Vh + ko);                                      \
            CP16(sb + FVL + d, g_Vl + ko);                                      \
        }                                                                       \
        CP_COMMIT();                                                            \
    }

    while (true) {
        if (tid == 0) t_sh = atomicAdd(&g_ctr, 1);
        __syncthreads();
        const int task = t_sh;
        if (task >= NTASKS) break;
        const int b  = task & 3;
        const int qt = 63 - (task >> 2);      // heavy-first (LPT)
        const int q0 = qt * 64;

        // group 1: Q + K(0); group 2: V(0)
        #pragma unroll
        for (int q = 0; q < 16; q++) {
            int u = tid + q * 128;
            int r = u >> 5, gg = u & 31;
            CP16(sb + FQ + r * 528 + gg * 16,
                 g_Q + ((size_t)(b*Tn + q0 + r)) * HD + gg * 4);
            CP16(sb + FK + r * 528 + gg * 16,
                 g_K + ((size_t)(b*Tn + r)) * HD + gg * 4);
        }
        CP_COMMIT();
        LOAD_V(b, 0);

        CP_WAIT1();                  // Q + K(0) resident
        __syncthreads();

        // ---- Q fragments -> registers (permuted: v2 gives a0,a2 / a1,a3) ----
        unsigned qreg[16][4];
        #pragma unroll
        for (int kc = 0; kc < 16; kc++) {
            unsigned ab = sb + FQ + (unsigned)(16*wid + g) * 528
                        + (unsigned)kc * 32 + (unsigned)t2 * 8;
            asm volatile("ld.shared.v2.b32 {%0,%1}, [%2];"
                         : "=r"(qreg[kc][0]), "=r"(qreg[kc][2]) : "r"(ab));
            asm volatile("ld.shared.v2.b32 {%0,%1}, [%2];"
                         : "=r"(qreg[kc][1]), "=r"(qreg[kc][3]) : "r"(ab + 8*528));
        }

        float o[16][4];
        #pragma unroll
        for (int i = 0; i < 16; i++)
            #pragma unroll
            for (int j = 0; j < 4; j++) o[i][j] = 0.f;
        float m_st[2] = {-1e30f, -1e30f};
        float l_st[2] = {0.f, 0.f};

        for (int kt = 0; kt <= qt; kt++) {
            CP_WAIT1();              // K(kt) complete
            __syncthreads();

            // ---- S = Q K^T  (tf32, Q in regs, K via v2; Q carries 1/sqrt(C)) ----
            float c[8][4];
            #pragma unroll
            for (int i = 0; i < 8; i++)
                #pragma unroll
                for (int j = 0; j < 4; j++) c[i][j] = 0.f;

            #pragma unroll
            for (int kc = 0; kc < 16; kc++) {
                #pragma unroll
                for (int np = 0; np < 8; np++) {
                    unsigned bb = sb + FK + (unsigned)(np*8 + g) * 528
                                + (unsigned)kc * 32 + (unsigned)t2 * 8;
                    unsigned b0, b1;
                    asm volatile("ld.shared.v2.b32 {%0,%1}, [%2];"
                                 : "=r"(b0), "=r"(b1) : "r"(bb));
                    mma1688t(c[np], qreg[kc], b0, b1);
                }
            }

            // ---- causal mask (diagonal tile only) ----
            if (kt == qt) {
                const int r0 = 16*wid + g, r1 = r0 + 8;
                #pragma unroll
                for (int nt = 0; nt < 8; nt++) {
                    int cb = 8*nt + 2*t2;
                    if (cb     > r0) c[nt][0] = -1e30f;
                    if (cb + 1 > r0) c[nt][1] = -1e30f;
                    if (cb     > r1) c[nt][2] = -1e30f;
                    if (cb + 1 > r1) c[nt][3] = -1e30f;
                }
            }

            // ---- online softmax on fragments (quad shfl) ----
            float corr[2];
            #pragma unroll
            for (int h = 0; h < 2; h++) {
                float mx = -1e30f;
                #pragma unroll
                for (int nt = 0; nt < 8; nt++)
                    mx = fmaxf(mx, fmaxf(c[nt][2*h], c[nt][2*h+1]));
                mx = fmaxf(mx, __shfl_xor_sync(0xffffffffu, mx, 1));
                mx = fmaxf(mx, __shfl_xor_sync(0xffffffffu, mx, 2));
                float mn = fmaxf(m_st[h], mx);
                corr[h] = __expf(m_st[h] - mn);
                m_st[h] = mn;
                float sum = 0.f;
                #pragma unroll
                for (int nt = 0; nt < 8; nt++) {
                    float p0 = __expf(c[nt][2*h]   - mn);
                    float p1 = __expf(c[nt][2*h+1] - mn);
                    c[nt][2*h] = p0; c[nt][2*h+1] = p1;
                    sum += p0 + p1;
                }
                sum += __shfl_xor_sync(0xffffffffu, sum, 1);
                sum += __shfl_xor_sync(0xffffffffu, sum, 2);
                l_st[h] = l_st[h] * corr[h] + sum;
            }

            CP_WAIT0();              // V(kt) complete
            __syncthreads();         // all warps past K reads
            if (kt < qt) LOAD_K(b, (kt + 1) * 64);   // prefetch K during PV

            // ---- rescale O ----
            #pragma unroll
            for (int nt = 0; nt < 16; nt++) {
                o[nt][0] *= corr[0]; o[nt][1] *= corr[0];
                o[nt][2] *= corr[1]; o[nt][3] *= corr[1];
            }

            // ---- P -> bf16 hi/lo A-fragments ----
            unsigned ph[4][4], pl[4][4];
            #pragma unroll
            for (int k2 = 0; k2 < 4; k2++) {
                #pragma unroll
                for (int j = 0; j < 4; j++) {
                    int nt = 2*k2 + (j >> 1);
                    float p0 = c[nt][(j & 1) * 2];
                    float p1 = c[nt][(j & 1) * 2 + 1];
                    float h0 = __bfloat162float(__float2bfloat16(p0));
                    float h1 = __bfloat162float(__float2bfloat16(p1));
                    ph[k2][j] = packbf(p0, p1);
                    pl[k2][j] = packbf(p0 - h0, p1 - h1);
                }
            }

            // ---- O += P V  (bf16, 3 products) ----
            #pragma unroll
            for (int np = 0; np < 8; np++) {
                #pragma unroll
                for (int k2 = 0; k2 < 4; k2++) {
                    unsigned vh[4], vl[4];
                    ldsm4t(vh[0], vh[1], vh[2], vh[3], faddr(sb + FVH, 16*k2, 2*np, lane));
                    ldsm4t(vl[0], vl[1], vl[2], vl[3], faddr(sb + FVL, 16*k2, 2*np, lane));
                    mma16816(o[2*np],   ph[k2], vh[0], vh[1]);
                    mma16816(o[2*np],   ph[k2], vl[0], vl[1]);
                    mma16816(o[2*np],   pl[k2], vh[0], vh[1]);
                    mma16816(o[2*np+1], ph[k2], vh[2], vh[3]);
                    mma16816(o[2*np+1], ph[k2], vl[2], vl[3]);
                    mma16816(o[2*np+1], pl[k2], vh[2], vh[3]);
                }
            }

            __syncthreads();         // all warps past V reads
            if (kt < qt) LOAD_V(b, (kt + 1) * 64);   // prefetch V during next S
        }

        // ---- normalize & write ----
        {
            float i0 = 1.f / l_st[0], i1 = 1.f / l_st[1];
            int r0 = q0 + 16*wid + g;
            #pragma unroll
            for (int nt = 0; nt < 16; nt++) {
                int col = 8*nt + 2*t2;
                *(float2*)&out[((size_t)b*Tn + r0)     * HD + col] =
                    make_float2(o[nt][0]*i0, o[nt][1]*i0);
                *(float2*)&out[((size_t)b*Tn + r0 + 8) * HD + col] =
                    make_float2(o[nt][2]*i1, o[nt][3]*i1);
            }
        }
    }
}

// ---------------------------------------------------------------------------
extern "C" void kernel_launch(void* const* d_in, const int* in_sizes, int n_in,
                              void* d_out, int out_size)
{
    const float* x  = (const float*)d_in[0];
    const float* Wq = (const float*)d_in[1];
    const float* Wk = (const float*)d_in[2];
    const float* Wv = (const float*)d_in[3];
    const float* cs = (const float*)d_in[4];
    const float* sn = (const float*)d_in[5];
    float* out = (float*)d_out;

    cudaFuncSetAttribute(gemm_qk_kernel,
                         cudaFuncAttributeMaxDynamicSharedMemorySize, QK_SMEM);
    cudaFuncSetAttribute(gemm_v_kernel,
                         cudaFuncAttributeMaxDynamicSharedMemorySize, V_SMEM);
    cudaFuncSetAttribute(flash_kernel,
                         cudaFuncAttributeMaxDynamicSharedMemorySize, FLASH_SMEM);

    wsplit_kernel<<<(3*NW4 + 255)/256, 256>>>(Wq, Wk, Wv);
    gemm_qk_kernel<<<dim3(2, Mn/64), 256, QK_SMEM>>>(x, cs, sn);
    gemm_v_kernel<<<dim3(1, Mn/64), 256, V_SMEM>>>(x);
    flash_kernel<<<296, 128, FLASH_SMEM>>>(out);
}

// round 15
// speedup vs baseline: 1.0887x; 1.0887x over previous
#include <cuda_runtime.h>
#include <cuda_bf16.h>
#include <math.h>
#include <stdint.h>

#define Bn 4
#define Tn 4096
#define Cn 2048
#define HD 128
#define Mn (Bn*Tn)
#define SCALE 0.022097086912079608f   // 1/sqrt(2048)

// ---------------- device scratch (static, no runtime alloc) ----------------
// g_wf uses PAIR-PERMUTED layout within each 8-float group (j<4?2j:2j-7).
__device__ float        g_wf[2*(size_t)HD*Cn];        // Wq, Wk (tf32, permuted)
__device__ __nv_bfloat16 g_wh[(size_t)HD*Cn];         // Wv hi
__device__ __nv_bfloat16 g_wl[(size_t)HD*Cn];         // Wv lo
__device__ __nv_bfloat16 g_Qh[(size_t)Mn*HD];         // bf16 (RoPE+scale applied)
__device__ __nv_bfloat16 g_Kh[(size_t)Mn*HD];         // bf16 (RoPE applied)
__device__ __nv_bfloat16 g_Vh[(size_t)Mn*HD], g_Vl[(size_t)Mn*HD];
__device__ int g_ctr;

// ---------------- base-ISA PTX helpers ---------------
__device__ __forceinline__ unsigned smem_u32(const void* p) {
    unsigned a;
    asm("{ .reg .u64 t; cvta.to.shared.u64 t, %1; cvt.u32.u64 %0, t; }" : "=r"(a) : "l"(p));
    return a;
}
#define CP16(dst, src) \
    asm volatile("cp.async.cg.shared.global [%0], [%1], 16;" \
                 :: "r"(dst), "l"(__cvta_generic_to_global((const void*)(src))) : "memory")
#define CP_COMMIT()  asm volatile("cp.async.commit_group;" ::: "memory")
#define CP_WAIT2()   asm volatile("cp.async.wait_group 2;" ::: "memory")
#define CP_WAIT1()   asm volatile("cp.async.wait_group 1;" ::: "memory")
#define CP_WAIT0()   asm volatile("cp.async.wait_group 0;" ::: "memory")

__device__ __forceinline__ void ldsm4(unsigned& r0, unsigned& r1, unsigned& r2, unsigned& r3,
                                      unsigned addr) {
    asm volatile("ldmatrix.sync.aligned.m8n8.x4.shared.b16 {%0,%1,%2,%3}, [%4];"
                 : "=r"(r0), "=r"(r1), "=r"(r2), "=r"(r3) : "r"(addr));
}
__device__ __forceinline__ void ldsm4t(unsigned& r0, unsigned& r1, unsigned& r2, unsigned& r3,
                                       unsigned addr) {
    asm volatile("ldmatrix.sync.aligned.m8n8.x4.trans.shared.b16 {%0,%1,%2,%3}, [%4];"
                 : "=r"(r0), "=r"(r1), "=r"(r2), "=r"(r3) : "r"(addr));
}
__device__ __forceinline__ void mma16816(float* c, const unsigned* a, unsigned b0, unsigned b1) {
    asm volatile(
        "mma.sync.aligned.m16n8k16.row.col.f32.bf16.bf16.f32 "
        "{%0,%1,%2,%3},{%4,%5,%6,%7},{%8,%9},{%0,%1,%2,%3};"
        : "+f"(c[0]), "+f"(c[1]), "+f"(c[2]), "+f"(c[3])
        : "r"(a[0]), "r"(a[1]), "r"(a[2]), "r"(a[3]), "r"(b0), "r"(b1));
}
__device__ __forceinline__ void mma1688t(float* c, const unsigned* a, unsigned b0, unsigned b1) {
    asm volatile(
        "mma.sync.aligned.m16n8k8.row.col.f32.tf32.tf32.f32 "
        "{%0,%1,%2,%3},{%4,%5,%6,%7},{%8,%9},{%0,%1,%2,%3};"
        : "+f"(c[0]), "+f"(c[1]), "+f"(c[2]), "+f"(c[3])
        : "r"(a[0]), "r"(a[1]), "r"(a[2]), "r"(a[3]), "r"(b0), "r"(b1));
}
__device__ __forceinline__ unsigned cvt_tf32(float f) {
    unsigned r; asm("cvt.rna.tf32.f32 %0, %1;" : "=r"(r) : "f"(f)); return r;
}
__device__ __forceinline__ unsigned packbf(float a, float b) {
    __nv_bfloat162 h = __floats2bfloat162_rn(a, b);
    return *(unsigned*)&h;
}
__device__ __forceinline__ void packhl(float a, float b, unsigned& h, unsigned& l) {
    __nv_bfloat162 hh = __floats2bfloat162_rn(a, b);
    unsigned hb = *(unsigned*)&hh;
    float fa = __uint_as_float(hb << 16);
    float fb = __uint_as_float(hb & 0xffff0000u);
    __nv_bfloat162 ll = __floats2bfloat162_rn(a - fa, b - fb);
    h = hb; l = *(unsigned*)&ll;
}

// ---------------------------------------------------------------------------
// weight prep: Wq,Wk -> tf32 fp32 PERMUTED; Wv -> bf16 hi/lo. Zeros counter.
// ---------------------------------------------------------------------------
#define NW4 (HD*Cn/4)          // 65536 float4 per weight

__global__ void wsplit_kernel(const float* __restrict__ Wq, const float* __restrict__ Wk,
                              const float* __restrict__ Wv)
{
    int i = blockIdx.x * blockDim.x + threadIdx.x;
    if (i == 0) g_ctr = 0;
    if (i >= 3 * NW4) return;
    int sel = i >> 16;
    int j   = i & (NW4 - 1);
    if (sel < 2) {
        const float* src = (sel == 0) ? Wq : Wk;
        float4 v = ((const float4*)src)[j];
        float* dst = g_wf + (size_t)sel * HD * Cn + (size_t)(j >> 1) * 8 + (j & 1);
        dst[0] = __uint_as_float(cvt_tf32(v.x));
        dst[2] = __uint_as_float(cvt_tf32(v.y));
        dst[4] = __uint_as_float(cvt_tf32(v.z));
        dst[6] = __uint_as_float(cvt_tf32(v.w));
    } else {
        float4 v = ((const float4*)Wv)[j];
        unsigned h0, l0, h1, l1;
        packhl(v.x, v.y, h0, l0);
        packhl(v.z, v.w, h1, l1);
        ((uint2*)g_wh)[j] = make_uint2(h0, h1);
        ((uint2*)g_wl)[j] = make_uint2(l0, l1);
    }
}

// ---------------------------------------------------------------------------
// Q/K projection GEMM, single-product tf32, permuted W (B-frag = 1 v2 LDS).
// Epilogue: RoPE (+scale on Q), store bf16 to g_Qh / g_Kh (plain layout).
// ---------------------------------------------------------------------------
#define QK_A_B   (64*144)
#define QK_W_OFF QK_A_B
#define QK_STAGE (QK_A_B + 128*144)      // 27648
#define QK_SMEM  (3*QK_STAGE)            // 82944

__global__ __launch_bounds__(256, 2) void gemm_qk_kernel(const float* __restrict__ x,
                                                         const float* __restrict__ cs,
                                                         const float* __restrict__ sn)
{
    extern __shared__ char gsm[];
    const int tid  = threadIdx.x;
    const int wid  = tid >> 5;
    const int lane = tid & 31;
    const int g    = lane >> 2;
    const int t2   = lane & 3;
    const int z    = blockIdx.x;                 // 0=Q, 1=K
    const int m0   = blockIdx.y * 64;
    const unsigned sbase = smem_u32(gsm);

    const float* xA = x + (size_t)m0 * Cn;
    const float* Wf = g_wf + (size_t)z * HD * Cn;

    #define QK_LOAD(cc, soff)                                                 \
    {                                                                         \
        int k0 = (cc) * 32;                                                   \
        _Pragma("unroll")                                                     \
        for (int q = 0; q < 2; q++) {                                         \
            int u = tid + q * 256;                                            \
            int row = u >> 3, gg = u & 7;                                     \
            CP16((soff) + sbase + row * 144 + gg * 16,                        \
                 xA + (size_t)row * Cn + k0 + gg * 4);                        \
        }                                                                     \
        _Pragma("unroll")                                                     \
        for (int q = 0; q < 4; q++) {                                         \
            int u = tid + q * 256;                                            \
            int row = u >> 3, gg = u & 7;                                     \
            CP16((soff) + sbase + QK_W_OFF + row * 144 + gg * 16,             \
                 Wf + (size_t)row * Cn + k0 + gg * 4);                        \
        }                                                                     \
        CP_COMMIT();                                                          \
    }

    const int wm = wid & 3;
    const int wn = wid >> 2;
    const int mrow0 = wm * 16;
    const int nrow0 = wn * 64;

    float c[8][4];
    #pragma unroll
    for (int b = 0; b < 8; b++)
        #pragma unroll
        for (int d = 0; d < 4; d++) c[b][d] = 0.f;

    QK_LOAD(0, 0u);
    QK_LOAD(1, (unsigned)QK_STAGE);

    for (int ch = 0; ch < 64; ch++) {
        const unsigned st = (unsigned)((ch % 3) * QK_STAGE);
        if (ch + 2 < 64) { QK_LOAD(ch + 2, (unsigned)(((ch + 2) % 3) * QK_STAGE)); CP_WAIT2(); }
        else if (ch + 1 < 64) { CP_WAIT1(); }
        else { CP_WAIT0(); }
        __syncthreads();

        #pragma unroll
        for (int k8 = 0; k8 < 4; k8++) {
            unsigned a[4];
            {
                unsigned ab = sbase + st + (unsigned)(mrow0 + g) * 144
                            + (unsigned)k8 * 32 + (unsigned)t2 * 4;
                float f0, f1, f2, f3;
                asm volatile("ld.shared.f32 %0, [%1];" : "=f"(f0) : "r"(ab));
                asm volatile("ld.shared.f32 %0, [%1];" : "=f"(f1) : "r"(ab + 8*144));
                asm volatile("ld.shared.f32 %0, [%1];" : "=f"(f2) : "r"(ab + 16));
                asm volatile("ld.shared.f32 %0, [%1];" : "=f"(f3) : "r"(ab + 8*144 + 16));
                a[0] = cvt_tf32(f0); a[1] = cvt_tf32(f1);
                a[2] = cvt_tf32(f2); a[3] = cvt_tf32(f3);
            }
            #pragma unroll
            for (int np = 0; np < 8; np++) {
                unsigned bb = sbase + st + QK_W_OFF
                            + (unsigned)(nrow0 + np * 8 + g) * 144
                            + (unsigned)k8 * 32 + (unsigned)t2 * 8;
                unsigned b0, b1;
                asm volatile("ld.shared.v2.b32 {%0,%1}, [%2];" : "=r"(b0), "=r"(b1) : "r"(bb));
                mma1688t(c[np], a, b0, b1);
            }
        }
        __syncthreads();
    }

    // epilogue: RoPE (+ scale on Q); store bf16 (plain layout)
    __nv_bfloat16* Out = (z == 0) ? g_Qh : g_Kh;
    {
        int mA = m0 + mrow0 + g;
        int tA = mA & (Tn - 1);
        #pragma unroll
        for (int np = 0; np < 8; np++) {
            int col = nrow0 + np * 8 + t2 * 2;
            int j = col >> 1;
            float c0 = cs[tA*64 + j],     s0 = sn[tA*64 + j];
            float c1 = cs[(tA+8)*64 + j], s1 = sn[(tA+8)*64 + j];
            float r0 = c[np][0]*c0 - c[np][1]*s0, i0 = c[np][0]*s0 + c[np][1]*c0;
            float r1 = c[np][2]*c1 - c[np][3]*s1, i1 = c[np][2]*s1 + c[np][3]*c1;
            if (z == 0) { r0 *= SCALE; i0 *= SCALE; r1 *= SCALE; i1 *= SCALE; }
            *(unsigned*)&Out[(size_t)mA * HD + col]       = packbf(r0, i0);
            *(unsigned*)&Out[(size_t)(mA + 8) * HD + col] = packbf(r1, i1);
        }
    }
}

// ---------------------------------------------------------------------------
// V projection GEMM: bf16 3-product (unchanged). grid (1, 256).
// ---------------------------------------------------------------------------
#define A_BYTES  (64*160)
#define BH_OFF   A_BYTES
#define BL_OFF   (A_BYTES + 8192)
#define STAGE_B  (A_BYTES + 16384)
#define V_SMEM   (3*STAGE_B)

__device__ __forceinline__ unsigned ldsm_addr(unsigned tile_base, int row0, int kg0, int lane) {
    int r  = row0 + (lane & 7) + ((lane >> 3) & 1) * 8;
    int kg = kg0 + (lane >> 4);
    return tile_base + r * 64 + (((unsigned)(kg ^ ((r >> 1) & 3))) << 4);
}

__device__ __forceinline__ void lda_frag(unsigned abase, int row0, int ks,
                                         int g, int t2, unsigned* ah, unsigned* al) {
    unsigned a0 = abase + (unsigned)(row0 + g) * 160 + (unsigned)ks * 64 + (unsigned)t2 * 8;
    float2 f01, f23, f45, f67;
    asm volatile("ld.shared.v2.f32 {%0,%1}, [%2];" : "=f"(f01.x), "=f"(f01.y) : "r"(a0));
    asm volatile("ld.shared.v2.f32 {%0,%1}, [%2];" : "=f"(f23.x), "=f"(f23.y) : "r"(a0 + 8*160));
    asm volatile("ld.shared.v2.f32 {%0,%1}, [%2];" : "=f"(f45.x), "=f"(f45.y) : "r"(a0 + 32));
    asm volatile("ld.shared.v2.f32 {%0,%1}, [%2];" : "=f"(f67.x), "=f"(f67.y) : "r"(a0 + 8*160 + 32));
    packhl(f01.x, f01.y, ah[0], al[0]);
    packhl(f23.x, f23.y, ah[1], al[1]);
    packhl(f45.x, f45.y, ah[2], al[2]);
    packhl(f67.x, f67.y, ah[3], al[3]);
}

__global__ __launch_bounds__(256, 2) void gemm_v_kernel(const float* __restrict__ x)
{
    extern __shared__ char gsm[];
    const int tid  = threadIdx.x;
    const int wid  = tid >> 5;
    const int lane = tid & 31;
    const int g    = lane >> 2;
    const int t2   = lane & 3;
    const int m0   = blockIdx.y * 64;
    const unsigned sbase = smem_u32(gsm);

    const float* xA = x + (size_t)m0 * Cn;
    const __nv_bfloat16* Bh = g_wh;
    const __nv_bfloat16* Bl = g_wl;

    #define V_LOAD(cc, soff)                                                      \
    {                                                                             \
        int k0 = (cc) * 32;                                                       \
        _Pragma("unroll")                                                         \
        for (int q = 0; q < 2; q++) {                                             \
            int u = tid + q * 256;                                                \
            int row = u >> 3, gg = u & 7;                                         \
            CP16((soff) + sbase + row * 160 + gg * 16,                            \
                 xA + (size_t)row * Cn + k0 + gg * 4);                            \
        }                                                                         \
        _Pragma("unroll")                                                         \
        for (int q = 0; q < 2; q++) {                                             \
            int row = (tid >> 2) + q * 64;                                        \
            int lg  = tid & 3;                                                    \
            unsigned d = (soff) + row * 64 + (((unsigned)(lg ^ ((row>>1)&3)))<<4);\
            size_t so = (size_t)row * Cn + k0 + lg * 8;                           \
            CP16(sbase + d + BH_OFF, Bh + so);                                    \
            CP16(sbase + d + BL_OFF, Bl + so);                                    \
        }                                                                         \
        CP_COMMIT();                                                              \
    }

    const int wm = wid & 3;
    const int wn = wid >> 2;
    const int mrow0 = wm * 16;
    const int nrow0 = wn * 64;

    float c[8][4];
    #pragma unroll
    for (int b = 0; b < 8; b++)
        #pragma unroll
        for (int d = 0; d < 4; d++) c[b][d] = 0.f;

    V_LOAD(0, 0u);
    V_LOAD(1, (unsigned)STAGE_B);

    for (int ch = 0; ch < 64; ch++) {
        const unsigned st = (unsigned)((ch % 3) * STAGE_B);
        if (ch + 2 < 64) { V_LOAD(ch + 2, (unsigned)(((ch + 2) % 3) * STAGE_B)); CP_WAIT2(); }
        else if (ch + 1 < 64) { CP_WAIT1(); }
        else { CP_WAIT0(); }
        __syncthreads();

        #pragma unroll
        for (int ks = 0; ks < 2; ks++) {
            const int kg0 = ks * 2;
            unsigned ah[4], al[4], bh[4][4], bl[4][4];
            lda_frag(sbase + st, mrow0, ks, g, t2, ah, al);
            #pragma unroll
            for (int np = 0; np < 4; np++) {
                unsigned aB = ldsm_addr(sbase + st + BH_OFF, nrow0 + np*16, kg0, lane);
                unsigned aC = ldsm_addr(sbase + st + BL_OFF, nrow0 + np*16, kg0, lane);
                ldsm4(bh[np][0], bh[np][1], bh[np][2], bh[np][3], aB);
                ldsm4(bl[np][0], bl[np][1], bl[np][2], bl[np][3], aC);
            }
            #pragma unroll
            for (int np = 0; np < 4; np++) {
                mma16816(c[np*2],   ah, bh[np][0], bh[np][2]);
                mma16816(c[np*2],   ah, bl[np][0], bl[np][2]);
                mma16816(c[np*2],   al, bh[np][0], bh[np][2]);
                mma16816(c[np*2+1], ah, bh[np][1], bh[np][3]);
                mma16816(c[np*2+1], ah, bl[np][1], bl[np][3]);
                mma16816(c[np*2+1], al, bh[np][1], bh[np][3]);
            }
        }
        __syncthreads();
    }

    {
        int mA = m0 + mrow0 + g;
        #pragma unroll
        for (int nt = 0; nt < 8; nt++) {
            int col = nrow0 + nt * 8 + t2 * 2;
            unsigned h, l;
            packhl(c[nt][0], c[nt][1], h, l);
            *(unsigned*)&g_Vh[(size_t)mA * HD + col] = h;
            *(unsigned*)&g_Vl[(size_t)mA * HD + col] = l;
            packhl(c[nt][2], c[nt][3], h, l);
            *(unsigned*)&g_Vh[(size_t)(mA + 8) * HD + col] = h;
            *(unsigned*)&g_Vl[(size_t)(mA + 8) * HD + col] = l;
        }
    }
}

// ---------------------------------------------------------------------------
// Flash attention: S = Qh.Kh (single bf16 product, ldmatrix), P.V bf16
// 3-product. smem 64KB (Qh|Kh|Vh|Vl, swizzled 256B rows) -> 3 CTAs/SM.
// ---------------------------------------------------------------------------
#define FQH 0
#define FKH 16384
#define FVH 32768
#define FVL 49152
#define FLASH_SMEM 65536
#define NTASKS (Bn * (Tn/64))    // 256

__device__ __forceinline__ unsigned faddr(unsigned base, int row0, int g0, int lane) {
    int r = row0 + (lane & 7) + ((lane >> 3) & 1) * 8;
    int g = g0 + (lane >> 4);
    return base + r * 256 + (((unsigned)(g ^ (r & 7))) << 4);
}

__global__ __launch_bounds__(128, 3) void flash_kernel(float* __restrict__ out)
{
    extern __shared__ char fsm[];
    __shared__ int t_sh;
    const unsigned sb = smem_u32(fsm);
    const int tid  = threadIdx.x;
    const int wid  = tid >> 5;
    const int lane = tid & 31;
    const int g    = lane >> 2;
    const int t2   = lane & 3;

    #define LOAD_K(b, k0)                                                       \
    {                                                                           \
        _Pragma("unroll")                                                       \
        for (int q = 0; q < 8; q++) {                                           \
            int u = tid + q * 128;                                              \
            int r = u >> 4, gg = u & 15;                                        \
            unsigned d = r * 256 + (((unsigned)(gg ^ (r & 7))) << 4);           \
            CP16(sb + FKH + d, g_Kh + ((size_t)((b)*Tn + (k0) + r)) * HD + gg * 8); \
        }                                                                       \
        CP_COMMIT();                                                            \
    }
    #define LOAD_V(b, k0)                                                       \
    {                                                                           \
        _Pragma("unroll")                                                       \
        for (int q = 0; q < 8; q++) {                                           \
            int u = tid + q * 128;                                              \
            int r = u >> 4, gg = u & 15;                                        \
            unsigned d = r * 256 + (((unsigned)(gg ^ (r & 7))) << 4);           \
            size_t ko = ((size_t)((b)*Tn + (k0) + r)) * HD + gg * 8;            \
            CP16(sb + FVH + d, g_Vh + ko);                                      \
            CP16(sb + FVL + d, g_Vl + ko);                                      \
        }                                                                       \
        CP_COMMIT();                                                            \
    }

    while (true) {
        if (tid == 0) t_sh = atomicAdd(&g_ctr, 1);
        __syncthreads();
        const int task = t_sh;
        if (task >= NTASKS) break;
        const int b  = task & 3;
        const int qt = 63 - (task >> 2);      // heavy-first (LPT)
        const int q0 = qt * 64;

        // group 1: Q + K(0); group 2: V(0)
        #pragma unroll
        for (int q = 0; q < 8; q++) {
            int u = tid + q * 128;
            int r = u >> 4, gg = u & 15;
            unsigned d = r * 256 + (((unsigned)(gg ^ (r & 7))) << 4);
            CP16(sb + FQH + d, g_Qh + ((size_t)(b*Tn + q0 + r)) * HD + gg * 8);
            CP16(sb + FKH + d, g_Kh + ((size_t)(b*Tn + r)) * HD + gg * 8);
        }
        CP_COMMIT();
        LOAD_V(b, 0);

        float o[16][4];
        #pragma unroll
        for (int i = 0; i < 16; i++)
            #pragma unroll
            for (int j = 0; j < 4; j++) o[i][j] = 0.f;
        float m_st[2] = {-1e30f, -1e30f};
        float l_st[2] = {0.f, 0.f};

        for (int kt = 0; kt <= qt; kt++) {
            CP_WAIT1();              // Q + K(kt) complete; V(kt) may be in flight
            __syncthreads();

            // ---- S = Qh Kh^T (single bf16 product; Q carries 1/sqrt(C)) ----
            float c[8][4];
            #pragma unroll
            for (int i = 0; i < 8; i++)
                #pragma unroll
                for (int j = 0; j < 4; j++) c[i][j] = 0.f;

            #pragma unroll
            for (int kc = 0; kc < 8; kc++) {
                unsigned qh[4];
                ldsm4(qh[0], qh[1], qh[2], qh[3], faddr(sb + FQH, 16*wid, 2*kc, lane));
                #pragma unroll
                for (int nb = 0; nb < 4; nb++) {
                    unsigned kh[4];
                    ldsm4(kh[0], kh[1], kh[2], kh[3], faddr(sb + FKH, 16*nb, 2*kc, lane));
                    mma16816(c[2*nb],   qh, kh[0], kh[2]);
                    mma16816(c[2*nb+1], qh, kh[1], kh[3]);
                }
            }

            // ---- causal mask (diagonal tile only) ----
            if (kt == qt) {
                const int r0 = 16*wid + g, r1 = r0 + 8;
                #pragma unroll
                for (int nt = 0; nt < 8; nt++) {
                    int cb = 8*nt + 2*t2;
                    if (cb     > r0) c[nt][0] = -1e30f;
                    if (cb + 1 > r0) c[nt][1] = -1e30f;
                    if (cb     > r1) c[nt][2] = -1e30f;
                    if (cb + 1 > r1) c[nt][3] = -1e30f;
                }
            }

            // ---- online softmax on fragments (quad shfl) ----
            float corr[2];
            #pragma unroll
            for (int h = 0; h < 2; h++) {
                float mx = -1e30f;
                #pragma unroll
                for (int nt = 0; nt < 8; nt++)
                    mx = fmaxf(mx, fmaxf(c[nt][2*h], c[nt][2*h+1]));
                mx = fmaxf(mx, __shfl_xor_sync(0xffffffffu, mx, 1));
                mx = fmaxf(mx, __shfl_xor_sync(0xffffffffu, mx, 2));
                float mn = fmaxf(m_st[h], mx);
                corr[h] = __expf(m_st[h] - mn);
                m_st[h] = mn;
                float sum = 0.f;
                #pragma unroll
                for (int nt = 0; nt < 8; nt++) {
                    float p0 = __expf(c[nt][2*h]   - mn);
                    float p1 = __expf(c[nt][2*h+1] - mn);
                    c[nt][2*h] = p0; c[nt][2*h+1] = p1;
                    sum += p0 + p1;
                }
                sum += __shfl_xor_sync(0xffffffffu, sum, 1);
                sum += __shfl_xor_sync(0xffffffffu, sum, 2);
                l_st[h] = l_st[h] * corr[h] + sum;
            }

            CP_WAIT0();              // V(kt) complete
            __syncthreads();         // all warps past K reads
            if (kt < qt) LOAD_K(b, (kt + 1) * 64);   // prefetch K during PV

            // ---- rescale O ----
            #pragma unroll
            for (int nt = 0; nt < 16; nt++) {
                o[nt][0] *= corr[0]; o[nt][1] *= corr[0];
                o[nt][2] *= corr[1]; o[nt][3] *= corr[1];
            }

            // ---- P -> bf16 hi/lo A-fragments ----
            unsigned ph[4][4], pl[4][4];
            #pragma unroll
            for (int k2 = 0; k2 < 4; k2++) {
                #pragma unroll
                for (int j = 0; j < 4; j++) {
                    int nt = 2*k2 + (j >> 1);
                    float p0 = c[nt][(j & 1) * 2];
                    float p1 = c[nt][(j & 1) * 2 + 1];
                    float h0 = __bfloat162float(__float2bfloat16(p0));
                    float h1 = __bfloat162float(__float2bfloat16(p1));
                    ph[k2][j] = packbf(p0, p1);
                    pl[k2][j] = packbf(p0 - h0, p1 - h1);
                }
            }

            // ---- O += P V  (bf16, 3 products) ----
            #pragma unroll
            for (int np = 0; np < 8; np++) {
                #pragma unroll
                for (int k2 = 0; k2 < 4; k2++) {
                    unsigned vh[4], vl[4];
                    ldsm4t(vh[0], vh[1], vh[2], vh[3], faddr(sb + FVH, 16*k2, 2*np, lane));
                    ldsm4t(vl[0], vl[1], vl[2], vl[3], faddr(sb + FVL, 16*k2, 2*np, lane));
                    mma16816(o[2*np],   ph[k2], vh[0], vh[1]);
                    mma16816(o[2*np],   ph[k2], vl[0], vl[1]);
                    mma16816(o[2*np],   pl[k2], vh[0], vh[1]);
                    mma16816(o[2*np+1], ph[k2], vh[2], vh[3]);
                    mma16816(o[2*np+1], ph[k2], vl[2], vl[3]);
                    mma16816(o[2*np+1], pl[k2], vh[2], vh[3]);
                }
            }

            __syncthreads();         // all warps past V reads
            if (kt < qt) LOAD_V(b, (kt + 1) * 64);   // prefetch V during next S
        }

        // ---- normalize & write ----
        {
            float i0 = 1.f / l_st[0], i1 = 1.f / l_st[1];
            int r0 = q0 + 16*wid + g;
            #pragma unroll
            for (int nt = 0; nt < 16; nt++) {
                int col = 8*nt + 2*t2;
                *(float2*)&out[((size_t)b*Tn + r0)     * HD + col] =
                    make_float2(o[nt][0]*i0, o[nt][1]*i0);
                *(float2*)&out[((size_t)b*Tn + r0 + 8) * HD + col] =
                    make_float2(o[nt][2]*i1, o[nt][3]*i1);
            }
        }
    }
}

// ---------------------------------------------------------------------------
extern "C" void kernel_launch(void* const* d_in, const int* in_sizes, int n_in,
                              void* d_out, int out_size)
{
    const float* x  = (const float*)d_in[0];
    const float* Wq = (const float*)d_in[1];
    const float* Wk = (const float*)d_in[2];
    const float* Wv = (const float*)d_in[3];
    const float* cs = (const float*)d_in[4];
    const float* sn = (const float*)d_in[5];
    float* out = (float*)d_out;

    cudaFuncSetAttribute(gemm_qk_kernel,
                         cudaFuncAttributeMaxDynamicSharedMemorySize, QK_SMEM);
    cudaFuncSetAttribute(gemm_v_kernel,
                         cudaFuncAttributeMaxDynamicSharedMemorySize, V_SMEM);
    cudaFuncSetAttribute(flash_kernel,
                         cudaFuncAttributeMaxDynamicSharedMemorySize, FLASH_SMEM);

    wsplit_kernel<<<(3*NW4 + 255)/256, 256>>>(Wq, Wk, Wv);
    gemm_qk_kernel<<<dim3(2, Mn/64), 256, QK_SMEM>>>(x, cs, sn);
    gemm_v_kernel<<<dim3(1, Mn/64), 256, V_SMEM>>>(x);
    flash_kernel<<<444, 128, FLASH_SMEM>>>(out);
}

// round 16
// speedup vs baseline: 1.5045x; 1.3819x over previous
#include <cuda_runtime.h>
#include <cuda_bf16.h>
#include <math.h>
#include <stdint.h>

#define Bn 4
#define Tn 4096
#define Cn 2048
#define HD 128
#define Mn (Bn*Tn)
#define SCALE 0.022097086912079608f   // 1/sqrt(2048)

// ---------------- device scratch (static, no runtime alloc) ----------------
__device__ float        g_wf[2*(size_t)HD*Cn];        // Wq, Wk (tf32-rounded fp32)
__device__ __nv_bfloat16 g_wh[(size_t)HD*Cn];         // Wv hi
__device__ __nv_bfloat16 g_wl[(size_t)HD*Cn];         // Wv lo
__device__ float        g_Q[(size_t)Mn*HD];           // tf32-rounded fp32
__device__ float        g_K[(size_t)Mn*HD];           // tf32-rounded fp32
__device__ __nv_bfloat16 g_Vh[(size_t)Mn*HD], g_Vl[(size_t)Mn*HD];
// split-K partials: 4 slots of (O unnorm, m, l)
__device__ float        g_Op[4*(size_t)Mn*HD];        // 32MB
__device__ float        g_ms[4*(size_t)Mn];
__device__ float        g_ls[4*(size_t)Mn];
__device__ int g_ctr;

// ---------------- base-ISA PTX helpers ---------------
__device__ __forceinline__ unsigned smem_u32(const void* p) {
    unsigned a;
    asm("{ .reg .u64 t; cvta.to.shared.u64 t, %1; cvt.u32.u64 %0, t; }" : "=r"(a) : "l"(p));
    return a;
}
#define CP16(dst, src) \
    asm volatile("cp.async.cg.shared.global [%0], [%1], 16;" \
                 :: "r"(dst), "l"(__cvta_generic_to_global((const void*)(src))) : "memory")
#define CP_COMMIT()  asm volatile("cp.async.commit_group;" ::: "memory")
#define CP_WAIT2()   asm volatile("cp.async.wait_group 2;" ::: "memory")
#define CP_WAIT1()   asm volatile("cp.async.wait_group 1;" ::: "memory")
#define CP_WAIT0()   asm volatile("cp.async.wait_group 0;" ::: "memory")

__device__ __forceinline__ void ldsm4(unsigned& r0, unsigned& r1, unsigned& r2, unsigned& r3,
                                      unsigned addr) {
    asm volatile("ldmatrix.sync.aligned.m8n8.x4.shared.b16 {%0,%1,%2,%3}, [%4];"
                 : "=r"(r0), "=r"(r1), "=r"(r2), "=r"(r3) : "r"(addr));
}
__device__ __forceinline__ void ldsm4t(unsigned& r0, unsigned& r1, unsigned& r2, unsigned& r3,
                                       unsigned addr) {
    asm volatile("ldmatrix.sync.aligned.m8n8.x4.trans.shared.b16 {%0,%1,%2,%3}, [%4];"
                 : "=r"(r0), "=r"(r1), "=r"(r2), "=r"(r3) : "r"(addr));
}
__device__ __forceinline__ void mma16816(float* c, const unsigned* a, unsigned b0, unsigned b1) {
    asm volatile(
        "mma.sync.aligned.m16n8k16.row.col.f32.bf16.bf16.f32 "
        "{%0,%1,%2,%3},{%4,%5,%6,%7},{%8,%9},{%0,%1,%2,%3};"
        : "+f"(c[0]), "+f"(c[1]), "+f"(c[2]), "+f"(c[3])
        : "r"(a[0]), "r"(a[1]), "r"(a[2]), "r"(a[3]), "r"(b0), "r"(b1));
}
__device__ __forceinline__ void mma1688t(float* c, const unsigned* a, unsigned b0, unsigned b1) {
    asm volatile(
        "mma.sync.aligned.m16n8k8.row.col.f32.tf32.tf32.f32 "
        "{%0,%1,%2,%3},{%4,%5,%6,%7},{%8,%9},{%0,%1,%2,%3};"
        : "+f"(c[0]), "+f"(c[1]), "+f"(c[2]), "+f"(c[3])
        : "r"(a[0]), "r"(a[1]), "r"(a[2]), "r"(a[3]), "r"(b0), "r"(b1));
}
__device__ __forceinline__ unsigned cvt_tf32(float f) {
    unsigned r; asm("cvt.rna.tf32.f32 %0, %1;" : "=r"(r) : "f"(f)); return r;
}
__device__ __forceinline__ unsigned packbf(float a, float b) {
    __nv_bfloat162 h = __floats2bfloat162_rn(a, b);
    return *(unsigned*)&h;
}
__device__ __forceinline__ void packhl(float a, float b, unsigned& h, unsigned& l) {
    __nv_bfloat162 hh = __floats2bfloat162_rn(a, b);
    unsigned hb = *(unsigned*)&hh;
    float fa = __uint_as_float(hb << 16);
    float fb = __uint_as_float(hb & 0xffff0000u);
    __nv_bfloat162 ll = __floats2bfloat162_rn(a - fa, b - fb);
    h = hb; l = *(unsigned*)&ll;
}

// ---------------------------------------------------------------------------
// weight prep: Wq,Wk -> tf32 fp32; Wv -> bf16 hi/lo. Zeros counter.
// ---------------------------------------------------------------------------
#define NW4 (HD*Cn/4)          // 65536 float4 per weight

__global__ void wsplit_kernel(const float* __restrict__ Wq, const float* __restrict__ Wk,
                              const float* __restrict__ Wv)
{
    int i = blockIdx.x * blockDim.x + threadIdx.x;
    if (i == 0) g_ctr = 0;
    if (i >= 3 * NW4) return;
    int sel = i >> 16;
    int j   = i & (NW4 - 1);
    if (sel < 2) {
        const float* src = (sel == 0) ? Wq : Wk;
        float4 v = ((const float4*)src)[j];
        float4 o;
        o.x = __uint_as_float(cvt_tf32(v.x));
        o.y = __uint_as_float(cvt_tf32(v.y));
        o.z = __uint_as_float(cvt_tf32(v.z));
        o.w = __uint_as_float(cvt_tf32(v.w));
        ((float4*)(g_wf + (size_t)sel * HD * Cn))[j] = o;
    } else {
        float4 v = ((const float4*)Wv)[j];
        unsigned h0, l0, h1, l1;
        packhl(v.x, v.y, h0, l0);
        packhl(v.z, v.w, h1, l1);
        ((uint2*)g_wh)[j] = make_uint2(h0, h1);
        ((uint2*)g_wl)[j] = make_uint2(l0, l1);
    }
}

// ---------------------------------------------------------------------------
// Q/K projection GEMM, single-product tf32 (R12-proven). grid (2, 256).
// ---------------------------------------------------------------------------
#define QK_A_B   (64*144)
#define QK_W_OFF QK_A_B
#define QK_STAGE (QK_A_B + 128*144)      // 27648
#define QK_SMEM  (3*QK_STAGE)            // 82944

__global__ __launch_bounds__(256, 2) void gemm_qk_kernel(const float* __restrict__ x,
                                                         const float* __restrict__ cs,
                                                         const float* __restrict__ sn)
{
    extern __shared__ char gsm[];
    const int tid  = threadIdx.x;
    const int wid  = tid >> 5;
    const int lane = tid & 31;
    const int g    = lane >> 2;
    const int t2   = lane & 3;
    const int z    = blockIdx.x;                 // 0=Q, 1=K
    const int m0   = blockIdx.y * 64;
    const unsigned sbase = smem_u32(gsm);

    const float* xA = x + (size_t)m0 * Cn;
    const float* Wf = g_wf + (size_t)z * HD * Cn;

    #define QK_LOAD(cc, soff)                                                 \
    {                                                                         \
        int k0 = (cc) * 32;                                                   \
        _Pragma("unroll")                                                     \
        for (int q = 0; q < 2; q++) {                                         \
            int u = tid + q * 256;                                            \
            int row = u >> 3, gg = u & 7;                                     \
            CP16((soff) + sbase + row * 144 + gg * 16,                        \
                 xA + (size_t)row * Cn + k0 + gg * 4);                        \
        }                                                                     \
        _Pragma("unroll")                                                     \
        for (int q = 0; q < 4; q++) {                                         \
            int u = tid + q * 256;                                            \
            int row = u >> 3, gg = u & 7;                                     \
            CP16((soff) + sbase + QK_W_OFF + row * 144 + gg * 16,             \
                 Wf + (size_t)row * Cn + k0 + gg * 4);                        \
        }                                                                     \
        CP_COMMIT();                                                          \
    }

    const int wm = wid & 3;
    const int wn = wid >> 2;
    const int mrow0 = wm * 16;
    const int nrow0 = wn * 64;

    float c[8][4];
    #pragma unroll
    for (int b = 0; b < 8; b++)
        #pragma unroll
        for (int d = 0; d < 4; d++) c[b][d] = 0.f;

    QK_LOAD(0, 0u);
    QK_LOAD(1, (unsigned)QK_STAGE);

    for (int ch = 0; ch < 64; ch++) {
        const unsigned st = (unsigned)((ch % 3) * QK_STAGE);
        if (ch + 2 < 64) { QK_LOAD(ch + 2, (unsigned)(((ch + 2) % 3) * QK_STAGE)); CP_WAIT2(); }
        else if (ch + 1 < 64) { CP_WAIT1(); }
        else { CP_WAIT0(); }
        __syncthreads();

        #pragma unroll
        for (int k8 = 0; k8 < 4; k8++) {
            unsigned a[4];
            {
                unsigned ab = sbase + st + (unsigned)(mrow0 + g) * 144
                            + (unsigned)k8 * 32 + (unsigned)t2 * 4;
                float f0, f1, f2, f3;
                asm volatile("ld.shared.f32 %0, [%1];" : "=f"(f0) : "r"(ab));
                asm volatile("ld.shared.f32 %0, [%1];" : "=f"(f1) : "r"(ab + 8*144));
                asm volatile("ld.shared.f32 %0, [%1];" : "=f"(f2) : "r"(ab + 16));
                asm volatile("ld.shared.f32 %0, [%1];" : "=f"(f3) : "r"(ab + 8*144 + 16));
                a[0] = cvt_tf32(f0); a[1] = cvt_tf32(f1);
                a[2] = cvt_tf32(f2); a[3] = cvt_tf32(f3);
            }
            #pragma unroll
            for (int np = 0; np < 8; np++) {
                unsigned bb = sbase + st + QK_W_OFF
                            + (unsigned)(nrow0 + np * 8 + g) * 144
                            + (unsigned)k8 * 32 + (unsigned)t2 * 4;
                unsigned b0, b1;
                asm volatile("ld.shared.b32 %0, [%1];" : "=r"(b0) : "r"(bb));
                asm volatile("ld.shared.b32 %0, [%1];" : "=r"(b1) : "r"(bb + 16));
                mma1688t(c[np], a, b0, b1);
            }
        }
        __syncthreads();
    }

    // epilogue: RoPE (+ scale on Q); store tf32-rounded fp32
    float* Out = (z == 0) ? g_Q : g_K;
    {
        int mA = m0 + mrow0 + g;
        int tA = mA & (Tn - 1);
        #pragma unroll
        for (int np = 0; np < 8; np++) {
            int col = nrow0 + np * 8 + t2 * 2;
            int j = col >> 1;
            float c0 = cs[tA*64 + j],     s0 = sn[tA*64 + j];
            float c1 = cs[(tA+8)*64 + j], s1 = sn[(tA+8)*64 + j];
            float r0 = c[np][0]*c0 - c[np][1]*s0, i0 = c[np][0]*s0 + c[np][1]*c0;
            float r1 = c[np][2]*c1 - c[np][3]*s1, i1 = c[np][2]*s1 + c[np][3]*c1;
            if (z == 0) { r0 *= SCALE; i0 *= SCALE; r1 *= SCALE; i1 *= SCALE; }
            float2 o0 = make_float2(__uint_as_float(cvt_tf32(r0)), __uint_as_float(cvt_tf32(i0)));
            float2 o1 = make_float2(__uint_as_float(cvt_tf32(r1)), __uint_as_float(cvt_tf32(i1)));
            *(float2*)&Out[(size_t)mA * HD + col]       = o0;
            *(float2*)&Out[(size_t)(mA + 8) * HD + col] = o1;
        }
    }
}

// ---------------------------------------------------------------------------
// V projection GEMM: bf16 3-product (unchanged). grid (1, 256).
// ---------------------------------------------------------------------------
#define A_BYTES  (64*160)
#define BH_OFF   A_BYTES
#define BL_OFF   (A_BYTES + 8192)
#define STAGE_B  (A_BYTES + 16384)
#define V_SMEM   (3*STAGE_B)

__device__ __forceinline__ unsigned ldsm_addr(unsigned tile_base, int row0, int kg0, int lane) {
    int r  = row0 + (lane & 7) + ((lane >> 3) & 1) * 8;
    int kg = kg0 + (lane >> 4);
    return tile_base + r * 64 + (((unsigned)(kg ^ ((r >> 1) & 3))) << 4);
}

__device__ __forceinline__ void lda_frag(unsigned abase, int row0, int ks,
                                         int g, int t2, unsigned* ah, unsigned* al) {
    unsigned a0 = abase + (unsigned)(row0 + g) * 160 + (unsigned)ks * 64 + (unsigned)t2 * 8;
    float2 f01, f23, f45, f67;
    asm volatile("ld.shared.v2.f32 {%0,%1}, [%2];" : "=f"(f01.x), "=f"(f01.y) : "r"(a0));
    asm volatile("ld.shared.v2.f32 {%0,%1}, [%2];" : "=f"(f23.x), "=f"(f23.y) : "r"(a0 + 8*160));
    asm volatile("ld.shared.v2.f32 {%0,%1}, [%2];" : "=f"(f45.x), "=f"(f45.y) : "r"(a0 + 32));
    asm volatile("ld.shared.v2.f32 {%0,%1}, [%2];" : "=f"(f67.x), "=f"(f67.y) : "r"(a0 + 8*160 + 32));
    packhl(f01.x, f01.y, ah[0], al[0]);
    packhl(f23.x, f23.y, ah[1], al[1]);
    packhl(f45.x, f45.y, ah[2], al[2]);
    packhl(f67.x, f67.y, ah[3], al[3]);
}

__global__ __launch_bounds__(256, 2) void gemm_v_kernel(const float* __restrict__ x)
{
    extern __shared__ char gsm[];
    const int tid  = threadIdx.x;
    const int wid  = tid >> 5;
    const int lane = tid & 31;
    const int g    = lane >> 2;
    const int t2   = lane & 3;
    const int m0   = blockIdx.y * 64;
    const unsigned sbase = smem_u32(gsm);

    const float* xA = x + (size_t)m0 * Cn;
    const __nv_bfloat16* Bh = g_wh;
    const __nv_bfloat16* Bl = g_wl;

    #define V_LOAD(cc, soff)                                                      \
    {                                                                             \
        int k0 = (cc) * 32;                                                       \
        _Pragma("unroll")                                                         \
        for (int q = 0; q < 2; q++) {                                             \
            int u = tid + q * 256;                                                \
            int row = u >> 3, gg = u & 7;                                         \
            CP16((soff) + sbase + row * 160 + gg * 16,                            \
                 xA + (size_t)row * Cn + k0 + gg * 4);                            \
        }                                                                         \
        _Pragma("unroll")                                                         \
        for (int q = 0; q < 2; q++) {                                             \
            int row = (tid >> 2) + q * 64;                                        \
            int lg  = tid & 3;                                                    \
            unsigned d = (soff) + row * 64 + (((unsigned)(lg ^ ((row>>1)&3)))<<4);\
            size_t so = (size_t)row * Cn + k0 + lg * 8;                           \
            CP16(sbase + d + BH_OFF, Bh + so);                                    \
            CP16(sbase + d + BL_OFF, Bl + so);                                    \
        }                                                                         \
        CP_COMMIT();                                                              \
    }

    const int wm = wid & 3;
    const int wn = wid >> 2;
    const int mrow0 = wm * 16;
    const int nrow0 = wn * 64;

    float c[8][4];
    #pragma unroll
    for (int b = 0; b < 8; b++)
        #pragma unroll
        for (int d = 0; d < 4; d++) c[b][d] = 0.f;

    V_LOAD(0, 0u);
    V_LOAD(1, (unsigned)STAGE_B);

    for (int ch = 0; ch < 64; ch++) {
        const unsigned st = (unsigned)((ch % 3) * STAGE_B);
        if (ch + 2 < 64) { V_LOAD(ch + 2, (unsigned)(((ch + 2) % 3) * STAGE_B)); CP_WAIT2(); }
        else if (ch + 1 < 64) { CP_WAIT1(); }
        else { CP_WAIT0(); }
        __syncthreads();

        #pragma unroll
        for (int ks = 0; ks < 2; ks++) {
            const int kg0 = ks * 2;
            unsigned ah[4], al[4], bh[4][4], bl[4][4];
            lda_frag(sbase + st, mrow0, ks, g, t2, ah, al);
            #pragma unroll
            for (int np = 0; np < 4; np++) {
                unsigned aB = ldsm_addr(sbase + st + BH_OFF, nrow0 + np*16, kg0, lane);
                unsigned aC = ldsm_addr(sbase + st + BL_OFF, nrow0 + np*16, kg0, lane);
                ldsm4(bh[np][0], bh[np][1], bh[np][2], bh[np][3], aB);
                ldsm4(bl[np][0], bl[np][1], bl[np][2], bl[np][3], aC);
            }
            #pragma unroll
            for (int np = 0; np < 4; np++) {
                mma16816(c[np*2],   ah, bh[np][0], bh[np][2]);
                mma16816(c[np*2],   ah, bl[np][0], bl[np][2]);
                mma16816(c[np*2],   al, bh[np][0], bh[np][2]);
                mma16816(c[np*2+1], ah, bh[np][1], bh[np][3]);
                mma16816(c[np*2+1], ah, bl[np][1], bl[np][3]);
                mma16816(c[np*2+1], al, bh[np][1], bh[np][3]);
            }
        }
        __syncthreads();
    }

    {
        int mA = m0 + mrow0 + g;
        #pragma unroll
        for (int nt = 0; nt < 8; nt++) {
            int col = nrow0 + nt * 8 + t2 * 2;
            unsigned h, l;
            packhl(c[nt][0], c[nt][1], h, l);
            *(unsigned*)&g_Vh[(size_t)mA * HD + col] = h;
            *(unsigned*)&g_Vl[(size_t)mA * HD + col] = l;
            packhl(c[nt][2], c[nt][3], h, l);
            *(unsigned*)&g_Vh[(size_t)(mA + 8) * HD + col] = h;
            *(unsigned*)&g_Vl[(size_t)(mA + 8) * HD + col] = l;
        }
    }
}

// ---------------------------------------------------------------------------
// Split-K flash attention (R12 per-tile pipeline, chunked work units).
// Chunk = (b, qt, ci): k-tiles [16ci, min(16ci+16, qt+1)). 640 chunks.
// Writes unnormalized partials (O, m, l) to slot ci; merge_kernel combines.
// smem: Q 64x528 | K 64x528 | Vh 16K | Vl 16K = 100352B -> 2 CTAs/SM.
// ---------------------------------------------------------------------------
#define FQ  0
#define FK  33792
#define FVH 67584
#define FVL 83968
#define FLASH_SMEM 100352
#define NCHUNK 640

__device__ __forceinline__ unsigned faddr(unsigned base, int row0, int g0, int lane) {
    int r = row0 + (lane & 7) + ((lane >> 3) & 1) * 8;
    int g = g0 + (lane >> 4);
    return base + r * 256 + (((unsigned)(g ^ (r & 7))) << 4);
}

__global__ __launch_bounds__(128, 2) void flash_kernel()
{
    extern __shared__ char fsm[];
    __shared__ int t_sh;
    const unsigned sb = smem_u32(fsm);
    const int tid  = threadIdx.x;
    const int wid  = tid >> 5;
    const int lane = tid & 31;
    const int g    = lane >> 2;
    const int t2   = lane & 3;

    #define LOAD_K(b, k0)                                                       \
    {                                                                           \
        _Pragma("unroll")                                                       \
        for (int q = 0; q < 16; q++) {                                          \
            int u = tid + q * 128;                                              \
            int r = u >> 5, gg = u & 31;                                        \
            CP16(sb + FK + r * 528 + gg * 16,                                   \
                 g_K + ((size_t)((b)*Tn + (k0) + r)) * HD + gg * 4);            \
        }                                                                       \
        CP_COMMIT();                                                            \
    }
    #define LOAD_V(b, k0)                                                       \
    {                                                                           \
        _Pragma("unroll")                                                       \
        for (int q = 0; q < 8; q++) {                                           \
            int u = tid + q * 128;                                              \
            int r = u >> 4, gg = u & 15;                                        \
            unsigned d = r * 256 + (((unsigned)(gg ^ (r & 7))) << 4);           \
            size_t ko = ((size_t)((b)*Tn + (k0) + r)) * HD + gg * 8;            \
            CP16(sb + FVH + d, g_Vh + ko);                                      \
            CP16(sb + FVL + d, g_Vl + ko);                                      \
        }                                                                       \
        CP_COMMIT();                                                            \
    }

    while (true) {
        if (tid == 0) t_sh = atomicAdd(&g_ctr, 1);
        __syncthreads();
        const int task = t_sh;
        if (task >= NCHUNK) break;

        // decode chunk: qt descending (LPT), then (ci, b)
        int rem = task, qt = 63;
        while (rem >= 4 * (qt / 16 + 1)) { rem -= 4 * (qt / 16 + 1); qt--; }
        const int b   = rem & 3;
        const int ci  = rem >> 2;
        const int q0  = qt * 64;
        const int kt0 = ci * 16;
        const int kt1 = min(kt0 + 16, qt + 1);

        // group 1: Q + K(kt0); group 2: V(kt0)
        #pragma unroll
        for (int q = 0; q < 16; q++) {
            int u = tid + q * 128;
            int r = u >> 5, gg = u & 31;
            CP16(sb + FQ + r * 528 + gg * 16,
                 g_Q + ((size_t)(b*Tn + q0 + r)) * HD + gg * 4);
            CP16(sb + FK + r * 528 + gg * 16,
                 g_K + ((size_t)(b*Tn + kt0*64 + r)) * HD + gg * 4);
        }
        CP_COMMIT();
        LOAD_V(b, kt0 * 64);

        float o[16][4];
        #pragma unroll
        for (int i = 0; i < 16; i++)
            #pragma unroll
            for (int j = 0; j < 4; j++) o[i][j] = 0.f;
        float m_st[2] = {-1e30f, -1e30f};
        float l_st[2] = {0.f, 0.f};

        for (int kt = kt0; kt < kt1; kt++) {
            CP_WAIT1();              // Q + K(kt) complete
            __syncthreads();

            // ---- S = Q K^T, single tf32 product (Q carries 1/sqrt(C)) ----
            float c[8][4];
            #pragma unroll
            for (int i = 0; i < 8; i++)
                #pragma unroll
                for (int j = 0; j < 4; j++) c[i][j] = 0.f;

            #pragma unroll
            for (int kc = 0; kc < 16; kc++) {
                unsigned a[4];
                {
                    unsigned ab = sb + FQ + (unsigned)(16*wid + g) * 528
                                + (unsigned)kc * 32 + (unsigned)t2 * 4;
                    asm volatile("ld.shared.b32 %0, [%1];" : "=r"(a[0]) : "r"(ab));
                    asm volatile("ld.shared.b32 %0, [%1];" : "=r"(a[1]) : "r"(ab + 8*528));
                    asm volatile("ld.shared.b32 %0, [%1];" : "=r"(a[2]) : "r"(ab + 16));
                    asm volatile("ld.shared.b32 %0, [%1];" : "=r"(a[3]) : "r"(ab + 8*528 + 16));
                }
                #pragma unroll
                for (int np = 0; np < 8; np++) {
                    unsigned bb = sb + FK + (unsigned)(np*8 + g) * 528
                                + (unsigned)kc * 32 + (unsigned)t2 * 4;
                    unsigned b0, b1;
                    asm volatile("ld.shared.b32 %0, [%1];" : "=r"(b0) : "r"(bb));
                    asm volatile("ld.shared.b32 %0, [%1];" : "=r"(b1) : "r"(bb + 16));
                    mma1688t(c[np], a, b0, b1);
                }
            }

            // ---- causal mask (diagonal tile only) ----
            if (kt == qt) {
                const int r0 = 16*wid + g, r1 = r0 + 8;
                #pragma unroll
                for (int nt = 0; nt < 8; nt++) {
                    int cb = 8*nt + 2*t2;
                    if (cb     > r0) c[nt][0] = -1e30f;
                    if (cb + 1 > r0) c[nt][1] = -1e30f;
                    if (cb     > r1) c[nt][2] = -1e30f;
                    if (cb + 1 > r1) c[nt][3] = -1e30f;
                }
            }

            // ---- online softmax on fragments (quad shfl) ----
            float corr[2];
            #pragma unroll
            for (int h = 0; h < 2; h++) {
                float mx = -1e30f;
                #pragma unroll
                for (int nt = 0; nt < 8; nt++)
                    mx = fmaxf(mx, fmaxf(c[nt][2*h], c[nt][2*h+1]));
                mx = fmaxf(mx, __shfl_xor_sync(0xffffffffu, mx, 1));
                mx = fmaxf(mx, __shfl_xor_sync(0xffffffffu, mx, 2));
                float mn = fmaxf(m_st[h], mx);
                corr[h] = __expf(m_st[h] - mn);
                m_st[h] = mn;
                float sum = 0.f;
                #pragma unroll
                for (int nt = 0; nt < 8; nt++) {
                    float p0 = __expf(c[nt][2*h]   - mn);
                    float p1 = __expf(c[nt][2*h+1] - mn);
                    c[nt][2*h] = p0; c[nt][2*h+1] = p1;
                    sum += p0 + p1;
                }
                sum += __shfl_xor_sync(0xffffffffu, sum, 1);
                sum += __shfl_xor_sync(0xffffffffu, sum, 2);
                l_st[h] = l_st[h] * corr[h] + sum;
            }

            CP_WAIT0();              // V(kt) complete
            __syncthreads();         // all warps past K reads
            if (kt + 1 < kt1) LOAD_K(b, (kt + 1) * 64);

            // ---- rescale O ----
            #pragma unroll
            for (int nt = 0; nt < 16; nt++) {
                o[nt][0] *= corr[0]; o[nt][1] *= corr[0];
                o[nt][2] *= corr[1]; o[nt][3] *= corr[1];
            }

            // ---- P -> bf16 hi/lo A-fragments ----
            unsigned ph[4][4], pl[4][4];
            #pragma unroll
            for (int k2 = 0; k2 < 4; k2++) {
                #pragma unroll
                for (int j = 0; j < 4; j++) {
                    int nt = 2*k2 + (j >> 1);
                    float p0 = c[nt][(j & 1) * 2];
                    float p1 = c[nt][(j & 1) * 2 + 1];
                    float h0 = __bfloat162float(__float2bfloat16(p0));
                    float h1 = __bfloat162float(__float2bfloat16(p1));
                    ph[k2][j] = packbf(p0, p1);
                    pl[k2][j] = packbf(p0 - h0, p1 - h1);
                }
            }

            // ---- O += P V  (bf16, 3 products) ----
            #pragma unroll
            for (int np = 0; np < 8; np++) {
                #pragma unroll
                for (int k2 = 0; k2 < 4; k2++) {
                    unsigned vh[4], vl[4];
                    ldsm4t(vh[0], vh[1], vh[2], vh[3], faddr(sb + FVH, 16*k2, 2*np, lane));
                    ldsm4t(vl[0], vl[1], vl[2], vl[3], faddr(sb + FVL, 16*k2, 2*np, lane));
                    mma16816(o[2*np],   ph[k2], vh[0], vh[1]);
                    mma16816(o[2*np],   ph[k2], vl[0], vl[1]);
                    mma16816(o[2*np],   pl[k2], vh[0], vh[1]);
                    mma16816(o[2*np+1], ph[k2], vh[2], vh[3]);
                    mma16816(o[2*np+1], ph[k2], vl[2], vl[3]);
                    mma16816(o[2*np+1], pl[k2], vh[2], vh[3]);
                }
            }

            __syncthreads();         // all warps past V reads
            if (kt + 1 < kt1) LOAD_V(b, (kt + 1) * 64);
        }

        // ---- write unnormalized partials to slot ci ----
        {
            float* Op = g_Op + (size_t)ci * Mn * HD;
            int r0 = 16*wid + g;
            size_t base0 = ((size_t)b*Tn + q0 + r0)     * HD;
            size_t base1 = ((size_t)b*Tn + q0 + r0 + 8) * HD;
            #pragma unroll
            for (int nt = 0; nt < 16; nt++) {
                int col = 8*nt + 2*t2;
                *(float2*)&Op[base0 + col] = make_float2(o[nt][0], o[nt][1]);
                *(float2*)&Op[base1 + col] = make_float2(o[nt][2], o[nt][3]);
            }
            if (t2 == 0) {
                size_t r = (size_t)ci * Mn + b*Tn + q0 + r0;
                g_ms[r]     = m_st[0];  g_ls[r]     = l_st[0];
                g_ms[r + 8] = m_st[1];  g_ls[r + 8] = l_st[1];
            }
        }
        __syncthreads();   // smem reuse safety before next chunk
    }
}

// ---------------------------------------------------------------------------
// merge split-K partials: out = (sum_i Op_i e^{m_i-m*}) / (sum_i l_i e^{m_i-m*})
// ---------------------------------------------------------------------------
__global__ void merge_kernel(float* __restrict__ out)
{
    int idx = blockIdx.x * blockDim.x + threadIdx.x;
    if (idx >= Mn * HD / 4) return;
    int row = idx >> 5;                 // HD/4 = 32 float4 per row
    int c4  = (idx & 31) * 4;
    int t   = row & (Tn - 1);
    int nc  = (t >> 6) / 16 + 1;        // chunks for this row's qt

    float m = -1e30f;
    for (int i = 0; i < nc; i++) m = fmaxf(m, g_ms[(size_t)i * Mn + row]);
    float L = 0.f;
    float4 acc = make_float4(0.f, 0.f, 0.f, 0.f);
    for (int i = 0; i < nc; i++) {
        float w = __expf(g_ms[(size_t)i * Mn + row] - m);
        L += g_ls[(size_t)i * Mn + row] * w;
        float4 v = *(const float4*)&g_Op[(size_t)i * Mn * HD + (size_t)row * HD + c4];
        acc.x += v.x * w; acc.y += v.y * w;
        acc.z += v.z * w; acc.w += v.w * w;
    }
    float inv = 1.f / L;
    *(float4*)&out[(size_t)row * HD + c4] =
        make_float4(acc.x * inv, acc.y * inv, acc.z * inv, acc.w * inv);
}

// ---------------------------------------------------------------------------
extern "C" void kernel_launch(void* const* d_in, const int* in_sizes, int n_in,
                              void* d_out, int out_size)
{
    const float* x  = (const float*)d_in[0];
    const float* Wq = (const float*)d_in[1];
    const float* Wk = (const float*)d_in[2];
    const float* Wv = (const float*)d_in[3];
    const float* cs = (const float*)d_in[4];
    const float* sn = (const float*)d_in[5];
    float* out = (float*)d_out;

    cudaFuncSetAttribute(gemm_qk_kernel,
                         cudaFuncAttributeMaxDynamicSharedMemorySize, QK_SMEM);
    cudaFuncSetAttribute(gemm_v_kernel,
                         cudaFuncAttributeMaxDynamicSharedMemorySize, V_SMEM);
    cudaFuncSetAttribute(flash_kernel,
                         cudaFuncAttributeMaxDynamicSharedMemorySize, FLASH_SMEM);

    wsplit_kernel<<<(3*NW4 + 255)/256, 256>>>(Wq, Wk, Wv);
    gemm_qk_kernel<<<dim3(2, Mn/64), 256, QK_SMEM>>>(x, cs, sn);
    gemm_v_kernel<<<dim3(1, Mn/64), 256, V_SMEM>>>(x);
    flash_kernel<<<296, 128, FLASH_SMEM>>>();
    merge_kernel<<<(Mn*HD/4 + 255)/256, 256>>>(out);
}

// round 17
// speedup vs baseline: 1.5853x; 1.0537x over previous
#include <cuda_runtime.h>
#include <cuda_bf16.h>
#include <math.h>
#include <stdint.h>

#define Bn 4
#define Tn 4096
#define Cn 2048
#define HD 128
#define Mn (Bn*Tn)
#define SCALE 0.022097086912079608f   // 1/sqrt(2048)

// ---------------- device scratch (static, no runtime alloc) ----------------
// g_wf uses PAIR-PERMUTED layout within each 8-float group: logical j ->
// physical (j<4 ? 2j : 2j-7), so (t2, t2+4) sit adjacent for v2 B-frag loads.
__device__ float        g_wf[2*(size_t)HD*Cn];        // Wq, Wk (tf32, permuted)
__device__ __nv_bfloat16 g_wh[(size_t)HD*Cn];         // Wv hi
__device__ __nv_bfloat16 g_wl[(size_t)HD*Cn];         // Wv lo
__device__ float        g_Q[(size_t)Mn*HD];           // tf32-rounded fp32
__device__ float        g_K[(size_t)Mn*HD];           // tf32-rounded fp32
__device__ __nv_bfloat16 g_Vh[(size_t)Mn*HD], g_Vl[(size_t)Mn*HD];
// split-K partials: 4 slots of (O unnorm, m, l)
__device__ float        g_Op[4*(size_t)Mn*HD];        // 32MB
__device__ float        g_ms[4*(size_t)Mn];
__device__ float        g_ls[4*(size_t)Mn];
__device__ int g_ctr;

// ---------------- base-ISA PTX helpers ---------------
__device__ __forceinline__ unsigned smem_u32(const void* p) {
    unsigned a;
    asm("{ .reg .u64 t; cvta.to.shared.u64 t, %1; cvt.u32.u64 %0, t; }" : "=r"(a) : "l"(p));
    return a;
}
#define CP16(dst, src) \
    asm volatile("cp.async.cg.shared.global [%0], [%1], 16;" \
                 :: "r"(dst), "l"(__cvta_generic_to_global((const void*)(src))) : "memory")
#define CP_COMMIT()  asm volatile("cp.async.commit_group;" ::: "memory")
#define CP_WAIT2()   asm volatile("cp.async.wait_group 2;" ::: "memory")
#define CP_WAIT1()   asm volatile("cp.async.wait_group 1;" ::: "memory")
#define CP_WAIT0()   asm volatile("cp.async.wait_group 0;" ::: "memory")

__device__ __forceinline__ void ldsm4(unsigned& r0, unsigned& r1, unsigned& r2, unsigned& r3,
                                      unsigned addr) {
    asm volatile("ldmatrix.sync.aligned.m8n8.x4.shared.b16 {%0,%1,%2,%3}, [%4];"
                 : "=r"(r0), "=r"(r1), "=r"(r2), "=r"(r3) : "r"(addr));
}
__device__ __forceinline__ void ldsm4t(unsigned& r0, unsigned& r1, unsigned& r2, unsigned& r3,
                                       unsigned addr) {
    asm volatile("ldmatrix.sync.aligned.m8n8.x4.trans.shared.b16 {%0,%1,%2,%3}, [%4];"
                 : "=r"(r0), "=r"(r1), "=r"(r2), "=r"(r3) : "r"(addr));
}
__device__ __forceinline__ void mma16816(float* c, const unsigned* a, unsigned b0, unsigned b1) {
    asm volatile(
        "mma.sync.aligned.m16n8k16.row.col.f32.bf16.bf16.f32 "
        "{%0,%1,%2,%3},{%4,%5,%6,%7},{%8,%9},{%0,%1,%2,%3};"
        : "+f"(c[0]), "+f"(c[1]), "+f"(c[2]), "+f"(c[3])
        : "r"(a[0]), "r"(a[1]), "r"(a[2]), "r"(a[3]), "r"(b0), "r"(b1));
}
__device__ __forceinline__ void mma1688t(float* c, const unsigned* a, unsigned b0, unsigned b1) {
    asm volatile(
        "mma.sync.aligned.m16n8k8.row.col.f32.tf32.tf32.f32 "
        "{%0,%1,%2,%3},{%4,%5,%6,%7},{%8,%9},{%0,%1,%2,%3};"
        : "+f"(c[0]), "+f"(c[1]), "+f"(c[2]), "+f"(c[3])
        : "r"(a[0]), "r"(a[1]), "r"(a[2]), "r"(a[3]), "r"(b0), "r"(b1));
}
__device__ __forceinline__ unsigned cvt_tf32(float f) {
    unsigned r; asm("cvt.rna.tf32.f32 %0, %1;" : "=r"(r) : "f"(f)); return r;
}
__device__ __forceinline__ unsigned packbf(float a, float b) {
    __nv_bfloat162 h = __floats2bfloat162_rn(a, b);
    return *(unsigned*)&h;
}
__device__ __forceinline__ void packhl(float a, float b, unsigned& h, unsigned& l) {
    __nv_bfloat162 hh = __floats2bfloat162_rn(a, b);
    unsigned hb = *(unsigned*)&hh;
    float fa = __uint_as_float(hb << 16);
    float fb = __uint_as_float(hb & 0xffff0000u);
    __nv_bfloat162 ll = __floats2bfloat162_rn(a - fa, b - fb);
    h = hb; l = *(unsigned*)&ll;
}

// ---------------------------------------------------------------------------
// weight prep: Wq,Wk -> tf32 fp32 PERMUTED; Wv -> bf16 hi/lo. Zeros counter.
// ---------------------------------------------------------------------------
#define NW4 (HD*Cn/4)          // 65536 float4 per weight

__global__ void wsplit_kernel(const float* __restrict__ Wq, const float* __restrict__ Wk,
                              const float* __restrict__ Wv)
{
    int i = blockIdx.x * blockDim.x + threadIdx.x;
    if (i == 0) g_ctr = 0;
    if (i >= 3 * NW4) return;
    int sel = i >> 16;
    int j   = i & (NW4 - 1);
    if (sel < 2) {
        const float* src = (sel == 0) ? Wq : Wk;
        float4 v = ((const float4*)src)[j];
        // group = j>>1 (8 floats); half = j&1. physical: j<4 -> 2j, j>=4 -> 2j-7
        float* dst = g_wf + (size_t)sel * HD * Cn + (size_t)(j >> 1) * 8 + (j & 1);
        dst[0] = __uint_as_float(cvt_tf32(v.x));
        dst[2] = __uint_as_float(cvt_tf32(v.y));
        dst[4] = __uint_as_float(cvt_tf32(v.z));
        dst[6] = __uint_as_float(cvt_tf32(v.w));
    } else {
        float4 v = ((const float4*)Wv)[j];
        unsigned h0, l0, h1, l1;
        packhl(v.x, v.y, h0, l0);
        packhl(v.z, v.w, h1, l1);
        ((uint2*)g_wh)[j] = make_uint2(h0, h1);
        ((uint2*)g_wl)[j] = make_uint2(l0, l1);
    }
}

// ---------------------------------------------------------------------------
// Q/K projection GEMM: M-tile 128, single-product tf32, permuted W (v2 B-frag),
// raw-fp32 A (HW-truncated tf32). grid (2, 128); 2 CTAs/SM; 3-stage pipeline.
// Stage: A fp32 128x144B | W fp32 128x144B = 36864B
// ---------------------------------------------------------------------------
#define QK_A_B   (128*144)               // 18432
#define QK_W_OFF QK_A_B
#define QK_STAGE (2*QK_A_B)              // 36864
#define QK_SMEM  (3*QK_STAGE)            // 110592

__global__ __launch_bounds__(256, 2) void gemm_qk_kernel(const float* __restrict__ x,
                                                         const float* __restrict__ cs,
                                                         const float* __restrict__ sn)
{
    extern __shared__ char gsm[];
    const int tid  = threadIdx.x;
    const int wid  = tid >> 5;
    const int lane = tid & 31;
    const int g    = lane >> 2;
    const int t2   = lane & 3;
    const int z    = blockIdx.x;                 // 0=Q, 1=K
    const int m0   = blockIdx.y * 128;
    const unsigned sbase = smem_u32(gsm);

    const float* xA = x + (size_t)m0 * Cn;
    const float* Wf = g_wf + (size_t)z * HD * Cn;

    #define QK_LOAD(cc, soff)                                                 \
    {                                                                         \
        int k0 = (cc) * 32;                                                   \
        _Pragma("unroll")                                                     \
        for (int q = 0; q < 4; q++) {                                         \
            int u = tid + q * 256;                                            \
            int row = u >> 3, gg = u & 7;                                     \
            CP16((soff) + sbase + row * 144 + gg * 16,                        \
                 xA + (size_t)row * Cn + k0 + gg * 4);                        \
            CP16((soff) + sbase + QK_W_OFF + row * 144 + gg * 16,             \
                 Wf + (size_t)row * Cn + k0 + gg * 4);                        \
        }                                                                     \
        CP_COMMIT();                                                          \
    }

    const int wm = wid & 3;              // 4 m-groups x 32 rows
    const int wn = wid >> 2;             // 2 n-groups x 64 cols
    const int mrow0 = wm * 32;
    const int nrow0 = wn * 64;

    float c[2][8][4];
    #pragma unroll
    for (int a = 0; a < 2; a++)
        #pragma unroll
        for (int b = 0; b < 8; b++)
            #pragma unroll
            for (int d = 0; d < 4; d++) c[a][b][d] = 0.f;

    QK_LOAD(0, 0u);
    QK_LOAD(1, (unsigned)QK_STAGE);

    for (int ch = 0; ch < 64; ch++) {
        const unsigned st = (unsigned)((ch % 3) * QK_STAGE);
        if (ch + 2 < 64) { QK_LOAD(ch + 2, (unsigned)(((ch + 2) % 3) * QK_STAGE)); CP_WAIT2(); }
        else if (ch + 1 < 64) { CP_WAIT1(); }
        else { CP_WAIT0(); }
        __syncthreads();

        #pragma unroll
        for (int k8 = 0; k8 < 4; k8++) {
            // A fragments: raw fp32 bits (HW truncates to tf32)
            unsigned a[2][4];
            #pragma unroll
            for (int mt = 0; mt < 2; mt++) {
                unsigned ab = sbase + st + (unsigned)(mrow0 + mt*16 + g) * 144
                            + (unsigned)k8 * 32 + (unsigned)t2 * 4;
                asm volatile("ld.shared.b32 %0, [%1];" : "=r"(a[mt][0]) : "r"(ab));
                asm volatile("ld.shared.b32 %0, [%1];" : "=r"(a[mt][1]) : "r"(ab + 8*144));
                asm volatile("ld.shared.b32 %0, [%1];" : "=r"(a[mt][2]) : "r"(ab + 16));
                asm volatile("ld.shared.b32 %0, [%1];" : "=r"(a[mt][3]) : "r"(ab + 8*144 + 16));
            }
            #pragma unroll
            for (int np = 0; np < 8; np++) {
                // permuted W: (t2, t2+4) adjacent -> single v2
                unsigned bb = sbase + st + QK_W_OFF
                            + (unsigned)(nrow0 + np * 8 + g) * 144
                            + (unsigned)k8 * 32 + (unsigned)t2 * 8;
                unsigned b0, b1;
                asm volatile("ld.shared.v2.b32 {%0,%1}, [%2];" : "=r"(b0), "=r"(b1) : "r"(bb));
                mma1688t(c[0][np], a[0], b0, b1);
                mma1688t(c[1][np], a[1], b0, b1);
            }
        }
        __syncthreads();
    }

    // epilogue: RoPE (+ scale on Q); store tf32-rounded fp32
    float* Out = (z == 0) ? g_Q : g_K;
    #pragma unroll
    for (int mt = 0; mt < 2; mt++) {
        int mA = m0 + mrow0 + mt * 16 + g;
        int tA = mA & (Tn - 1);
        #pragma unroll
        for (int np = 0; np < 8; np++) {
            int col = nrow0 + np * 8 + t2 * 2;
            int j = col >> 1;
            float c0 = cs[tA*64 + j],     s0 = sn[tA*64 + j];
            float c1 = cs[(tA+8)*64 + j], s1 = sn[(tA+8)*64 + j];
            float r0 = c[mt][np][0]*c0 - c[mt][np][1]*s0;
            float i0 = c[mt][np][0]*s0 + c[mt][np][1]*c0;
            float r1 = c[mt][np][2]*c1 - c[mt][np][3]*s1;
            float i1 = c[mt][np][2]*s1 + c[mt][np][3]*c1;
            if (z == 0) { r0 *= SCALE; i0 *= SCALE; r1 *= SCALE; i1 *= SCALE; }
            float2 o0 = make_float2(__uint_as_float(cvt_tf32(r0)), __uint_as_float(cvt_tf32(i0)));
            float2 o1 = make_float2(__uint_as_float(cvt_tf32(r1)), __uint_as_float(cvt_tf32(i1)));
            *(float2*)&Out[(size_t)mA * HD + col]       = o0;
            *(float2*)&Out[(size_t)(mA + 8) * HD + col] = o1;
        }
    }
}

// ---------------------------------------------------------------------------
// V projection GEMM: bf16 3-product (unchanged — near tensor floor).
// ---------------------------------------------------------------------------
#define A_BYTES  (64*160)
#define BH_OFF   A_BYTES
#define BL_OFF   (A_BYTES + 8192)
#define STAGE_B  (A_BYTES + 16384)
#define V_SMEM   (3*STAGE_B)

__device__ __forceinline__ unsigned ldsm_addr(unsigned tile_base, int row0, int kg0, int lane) {
    int r  = row0 + (lane & 7) + ((lane >> 3) & 1) * 8;
    int kg = kg0 + (lane >> 4);
    return tile_base + r * 64 + (((unsigned)(kg ^ ((r >> 1) & 3))) << 4);
}

__device__ __forceinline__ void lda_frag(unsigned abase, int row0, int ks,
                                         int g, int t2, unsigned* ah, unsigned* al) {
    unsigned a0 = abase + (unsigned)(row0 + g) * 160 + (unsigned)ks * 64 + (unsigned)t2 * 8;
    float2 f01, f23, f45, f67;
    asm volatile("ld.shared.v2.f32 {%0,%1}, [%2];" : "=f"(f01.x), "=f"(f01.y) : "r"(a0));
    asm volatile("ld.shared.v2.f32 {%0,%1}, [%2];" : "=f"(f23.x), "=f"(f23.y) : "r"(a0 + 8*160));
    asm volatile("ld.shared.v2.f32 {%0,%1}, [%2];" : "=f"(f45.x), "=f"(f45.y) : "r"(a0 + 32));
    asm volatile("ld.shared.v2.f32 {%0,%1}, [%2];" : "=f"(f67.x), "=f"(f67.y) : "r"(a0 + 8*160 + 32));
    packhl(f01.x, f01.y, ah[0], al[0]);
    packhl(f23.x, f23.y, ah[1], al[1]);
    packhl(f45.x, f45.y, ah[2], al[2]);
    packhl(f67.x, f67.y, ah[3], al[3]);
}

__global__ __launch_bounds__(256, 2) void gemm_v_kernel(const float* __restrict__ x)
{
    extern __shared__ char gsm[];
    const int tid  = threadIdx.x;
    const int wid  = tid >> 5;
    const int lane = tid & 31;
    const int g    = lane >> 2;
    const int t2   = lane & 3;
    const int m0   = blockIdx.y * 64;
    const unsigned sbase = smem_u32(gsm);

    const float* xA = x + (size_t)m0 * Cn;
    const __nv_bfloat16* Bh = g_wh;
    const __nv_bfloat16* Bl = g_wl;

    #define V_LOAD(cc, soff)                                                      \
    {                                                                             \
        int k0 = (cc) * 32;                                                       \
        _Pragma("unroll")                                                         \
        for (int q = 0; q < 2; q++) {                                             \
            int u = tid + q * 256;                                                \
            int row = u >> 3, gg = u & 7;                                         \
            CP16((soff) + sbase + row * 160 + gg * 16,                            \
                 xA + (size_t)row * Cn + k0 + gg * 4);                            \
        }                                                                         \
        _Pragma("unroll")                                                         \
        for (int q = 0; q < 2; q++) {                                             \
            int row = (tid >> 2) + q * 64;                                        \
            int lg  = tid & 3;                                                    \
            unsigned d = (soff) + row * 64 + (((unsigned)(lg ^ ((row>>1)&3)))<<4);\
            size_t so = (size_t)row * Cn + k0 + lg * 8;                           \
            CP16(sbase + d + BH_OFF, Bh + so);                                    \
            CP16(sbase + d + BL_OFF, Bl + so);                                    \
        }                                                                         \
        CP_COMMIT();                                                              \
    }

    const int wm = wid & 3;
    const int wn = wid >> 2;
    const int mrow0 = wm * 16;
    const int nrow0 = wn * 64;

    float c[8][4];
    #pragma unroll
    for (int b = 0; b < 8; b++)
        #pragma unroll
        for (int d = 0; d < 4; d++) c[b][d] = 0.f;

    V_LOAD(0, 0u);
    V_LOAD(1, (unsigned)STAGE_B);

    for (int ch = 0; ch < 64; ch++) {
        const unsigned st = (unsigned)((ch % 3) * STAGE_B);
        if (ch + 2 < 64) { V_LOAD(ch + 2, (unsigned)(((ch + 2) % 3) * STAGE_B)); CP_WAIT2(); }
        else if (ch + 1 < 64) { CP_WAIT1(); }
        else { CP_WAIT0(); }
        __syncthreads();

        #pragma unroll
        for (int ks = 0; ks < 2; ks++) {
            const int kg0 = ks * 2;
            unsigned ah[4], al[4], bh[4][4], bl[4][4];
            lda_frag(sbase + st, mrow0, ks, g, t2, ah, al);
            #pragma unroll
            for (int np = 0; np < 4; np++) {
                unsigned aB = ldsm_addr(sbase + st + BH_OFF, nrow0 + np*16, kg0, lane);
                unsigned aC = ldsm_addr(sbase + st + BL_OFF, nrow0 + np*16, kg0, lane);
                ldsm4(bh[np][0], bh[np][1], bh[np][2], bh[np][3], aB);
                ldsm4(bl[np][0], bl[np][1], bl[np][2], bl[np][3], aC);
            }
            #pragma unroll
            for (int np = 0; np < 4; np++) {
                mma16816(c[np*2],   ah, bh[np][0], bh[np][2]);
                mma16816(c[np*2],   ah, bl[np][0], bl[np][2]);
                mma16816(c[np*2],   al, bh[np][0], bh[np][2]);
                mma16816(c[np*2+1], ah, bh[np][1], bh[np][3]);
                mma16816(c[np*2+1], ah, bl[np][1], bl[np][3]);
                mma16816(c[np*2+1], al, bh[np][1], bh[np][3]);
            }
        }
        __syncthreads();
    }

    {
        int mA = m0 + mrow0 + g;
        #pragma unroll
        for (int nt = 0; nt < 8; nt++) {
            int col = nrow0 + nt * 8 + t2 * 2;
            unsigned h, l;
            packhl(c[nt][0], c[nt][1], h, l);
            *(unsigned*)&g_Vh[(size_t)mA * HD + col] = h;
            *(unsigned*)&g_Vl[(size_t)mA * HD + col] = l;
            packhl(c[nt][2], c[nt][3], h, l);
            *(unsigned*)&g_Vh[(size_t)(mA + 8) * HD + col] = h;
            *(unsigned*)&g_Vl[(size_t)(mA + 8) * HD + col] = l;
        }
    }
}

// ---------------------------------------------------------------------------
// Split-K flash attention (R16-proven, unchanged).
// Chunk = (b, qt, ci): k-tiles [16ci, min(16ci+16, qt+1)). 640 chunks.
// ---------------------------------------------------------------------------
#define FQ  0
#define FK  33792
#define FVH 67584
#define FVL 83968
#define FLASH_SMEM 100352
#define NCHUNK 640

__device__ __forceinline__ unsigned faddr(unsigned base, int row0, int g0, int lane) {
    int r = row0 + (lane & 7) + ((lane >> 3) & 1) * 8;
    int g = g0 + (lane >> 4);
    return base + r * 256 + (((unsigned)(g ^ (r & 7))) << 4);
}

__global__ __launch_bounds__(128, 2) void flash_kernel()
{
    extern __shared__ char fsm[];
    __shared__ int t_sh;
    const unsigned sb = smem_u32(fsm);
    const int tid  = threadIdx.x;
    const int wid  = tid >> 5;
    const int lane = tid & 31;
    const int g    = lane >> 2;
    const int t2   = lane & 3;

    #define LOAD_K(b, k0)                                                       \
    {                                                                           \
        _Pragma("unroll")                                                       \
        for (int q = 0; q < 16; q++) {                                          \
            int u = tid + q * 128;                                              \
            int r = u >> 5, gg = u & 31;                                        \
            CP16(sb + FK + r * 528 + gg * 16,                                   \
                 g_K + ((size_t)((b)*Tn + (k0) + r)) * HD + gg * 4);            \
        }                                                                       \
        CP_COMMIT();                                                            \
    }
    #define LOAD_V(b, k0)                                                       \
    {                                                                           \
        _Pragma("unroll")                                                       \
        for (int q = 0; q < 8; q++) {                                           \
            int u = tid + q * 128;                                              \
            int r = u >> 4, gg = u & 15;                                        \
            unsigned d = r * 256 + (((unsigned)(gg ^ (r & 7))) << 4);           \
            size_t ko = ((size_t)((b)*Tn + (k0) + r)) * HD + gg * 8;            \
            CP16(sb + FVH + d, g_Vh + ko);                                      \
            CP16(sb + FVL + d, g_Vl + ko);                                      \
        }                                                                       \
        CP_COMMIT();                                                            \
    }

    while (true) {
        if (tid == 0) t_sh = atomicAdd(&g_ctr, 1);
        __syncthreads();
        const int task = t_sh;
        if (task >= NCHUNK) break;

        // decode chunk: qt descending (LPT), then (ci, b)
        int rem = task, qt = 63;
        while (rem >= 4 * (qt / 16 + 1)) { rem -= 4 * (qt / 16 + 1); qt--; }
        const int b   = rem & 3;
        const int ci  = rem >> 2;
        const int q0  = qt * 64;
        const int kt0 = ci * 16;
        const int kt1 = min(kt0 + 16, qt + 1);

        // group 1: Q + K(kt0); group 2: V(kt0)
        #pragma unroll
        for (int q = 0; q < 16; q++) {
            int u = tid + q * 128;
            int r = u >> 5, gg = u & 31;
            CP16(sb + FQ + r * 528 + gg * 16,
                 g_Q + ((size_t)(b*Tn + q0 + r)) * HD + gg * 4);
            CP16(sb + FK + r * 528 + gg * 16,
                 g_K + ((size_t)(b*Tn + kt0*64 + r)) * HD + gg * 4);
        }
        CP_COMMIT();
        LOAD_V(b, kt0 * 64);

        float o[16][4];
        #pragma unroll
        for (int i = 0; i < 16; i++)
            #pragma unroll
            for (int j = 0; j < 4; j++) o[i][j] = 0.f;
        float m_st[2] = {-1e30f, -1e30f};
        float l_st[2] = {0.f, 0.f};

        for (int kt = kt0; kt < kt1; kt++) {
            CP_WAIT1();              // Q + K(kt) complete
            __syncthreads();

            // ---- S = Q K^T, single tf32 product (Q carries 1/sqrt(C)) ----
            float c[8][4];
            #pragma unroll
            for (int i = 0; i < 8; i++)
                #pragma unroll
                for (int j = 0; j < 4; j++) c[i][j] = 0.f;

            #pragma unroll
            for (int kc = 0; kc < 16; kc++) {
                unsigned a[4];
                {
                    unsigned ab = sb + FQ + (unsigned)(16*wid + g) * 528
                                + (unsigned)kc * 32 + (unsigned)t2 * 4;
                    asm volatile("ld.shared.b32 %0, [%1];" : "=r"(a[0]) : "r"(ab));
                    asm volatile("ld.shared.b32 %0, [%1];" : "=r"(a[1]) : "r"(ab + 8*528));
                    asm volatile("ld.shared.b32 %0, [%1];" : "=r"(a[2]) : "r"(ab + 16));
                    asm volatile("ld.shared.b32 %0, [%1];" : "=r"(a[3]) : "r"(ab + 8*528 + 16));
                }
                #pragma unroll
                for (int np = 0; np < 8; np++) {
                    unsigned bb = sb + FK + (unsigned)(np*8 + g) * 528
                                + (unsigned)kc * 32 + (unsigned)t2 * 4;
                    unsigned b0, b1;
                    asm volatile("ld.shared.b32 %0, [%1];" : "=r"(b0) : "r"(bb));
                    asm volatile("ld.shared.b32 %0, [%1];" : "=r"(b1) : "r"(bb + 16));
                    mma1688t(c[np], a, b0, b1);
                }
            }

            // ---- causal mask (diagonal tile only) ----
            if (kt == qt) {
                const int r0 = 16*wid + g, r1 = r0 + 8;
                #pragma unroll
                for (int nt = 0; nt < 8; nt++) {
                    int cb = 8*nt + 2*t2;
                    if (cb     > r0) c[nt][0] = -1e30f;
                    if (cb + 1 > r0) c[nt][1] = -1e30f;
                    if (cb     > r1) c[nt][2] = -1e30f;
                    if (cb + 1 > r1) c[nt][3] = -1e30f;
                }
            }

            // ---- online softmax on fragments (quad shfl) ----
            float corr[2];
            #pragma unroll
            for (int h = 0; h < 2; h++) {
                float mx = -1e30f;
                #pragma unroll
                for (int nt = 0; nt < 8; nt++)
                    mx = fmaxf(mx, fmaxf(c[nt][2*h], c[nt][2*h+1]));
                mx = fmaxf(mx, __shfl_xor_sync(0xffffffffu, mx, 1));
                mx = fmaxf(mx, __shfl_xor_sync(0xffffffffu, mx, 2));
                float mn = fmaxf(m_st[h], mx);
                corr[h] = __expf(m_st[h] - mn);
                m_st[h] = mn;
                float sum = 0.f;
                #pragma unroll
                for (int nt = 0; nt < 8; nt++) {
                    float p0 = __expf(c[nt][2*h]   - mn);
                    float p1 = __expf(c[nt][2*h+1] - mn);
                    c[nt][2*h] = p0; c[nt][2*h+1] = p1;
                    sum += p0 + p1;
                }
                sum += __shfl_xor_sync(0xffffffffu, sum, 1);
                sum += __shfl_xor_sync(0xffffffffu, sum, 2);
                l_st[h] = l_st[h] * corr[h] + sum;
            }

            CP_WAIT0();              // V(kt) complete
            __syncthreads();         // all warps past K reads
            if (kt + 1 < kt1) LOAD_K(b, (kt + 1) * 64);

            // ---- rescale O ----
            #pragma unroll
            for (int nt = 0; nt < 16; nt++) {
                o[nt][0] *= corr[0]; o[nt][1] *= corr[0];
                o[nt][2] *= corr[1]; o[nt][3] *= corr[1];
            }

            // ---- P -> bf16 hi/lo A-fragments ----
            unsigned ph[4][4], pl[4][4];
            #pragma unroll
            for (int k2 = 0; k2 < 4; k2++) {
                #pragma unroll
                for (int j = 0; j < 4; j++) {
                    int nt = 2*k2 + (j >> 1);
                    float p0 = c[nt][(j & 1) * 2];
                    float p1 = c[nt][(j & 1) * 2 + 1];
                    float h0 = __bfloat162float(__float2bfloat16(p0));
                    float h1 = __bfloat162float(__float2bfloat16(p1));
                    ph[k2][j] = packbf(p0, p1);
                    pl[k2][j] = packbf(p0 - h0, p1 - h1);
                }
            }

            // ---- O += P V  (bf16, 3 products) ----
            #pragma unroll
            for (int np = 0; np < 8; np++) {
                #pragma unroll
                for (int k2 = 0; k2 < 4; k2++) {
                    unsigned vh[4], vl[4];
                    ldsm4t(vh[0], vh[1], vh[2], vh[3], faddr(sb + FVH, 16*k2, 2*np, lane));
                    ldsm4t(vl[0], vl[1], vl[2], vl[3], faddr(sb + FVL, 16*k2, 2*np, lane));
                    mma16816(o[2*np],   ph[k2], vh[0], vh[1]);
                    mma16816(o[2*np],   ph[k2], vl[0], vl[1]);
                    mma16816(o[2*np],   pl[k2], vh[0], vh[1]);
                    mma16816(o[2*np+1], ph[k2], vh[2], vh[3]);
                    mma16816(o[2*np+1], ph[k2], vl[2], vl[3]);
                    mma16816(o[2*np+1], pl[k2], vh[2], vh[3]);
                }
            }

            __syncthreads();         // all warps past V reads
            if (kt + 1 < kt1) LOAD_V(b, (kt + 1) * 64);
        }

        // ---- write unnormalized partials to slot ci ----
        {
            float* Op = g_Op + (size_t)ci * Mn * HD;
            int r0 = 16*wid + g;
            size_t base0 = ((size_t)b*Tn + q0 + r0)     * HD;
            size_t base1 = ((size_t)b*Tn + q0 + r0 + 8) * HD;
            #pragma unroll
            for (int nt = 0; nt < 16; nt++) {
                int col = 8*nt + 2*t2;
                *(float2*)&Op[base0 + col] = make_float2(o[nt][0], o[nt][1]);
                *(float2*)&Op[base1 + col] = make_float2(o[nt][2], o[nt][3]);
            }
            if (t2 == 0) {
                size_t r = (size_t)ci * Mn + b*Tn + q0 + r0;
                g_ms[r]     = m_st[0];  g_ls[r]     = l_st[0];
                g_ms[r + 8] = m_st[1];  g_ls[r + 8] = l_st[1];
            }
        }
        __syncthreads();   // smem reuse safety before next chunk
    }
}

// ---------------------------------------------------------------------------
// merge split-K partials
// ---------------------------------------------------------------------------
__global__ void merge_kernel(float* __restrict__ out)
{
    int idx = blockIdx.x * blockDim.x + threadIdx.x;
    if (idx >= Mn * HD / 4) return;
    int row = idx >> 5;
    int c4  = (idx & 31) * 4;
    int t   = row & (Tn - 1);
    int nc  = (t >> 6) / 16 + 1;

    float m = -1e30f;
    for (int i = 0; i < nc; i++) m = fmaxf(m, g_ms[(size_t)i * Mn + row]);
    float L = 0.f;
    float4 acc = make_float4(0.f, 0.f, 0.f, 0.f);
    for (int i = 0; i < nc; i++) {
        float w = __expf(g_ms[(size_t)i * Mn + row] - m);
        L += g_ls[(size_t)i * Mn + row] * w;
        float4 v = *(const float4*)&g_Op[(size_t)i * Mn * HD + (size_t)row * HD + c4];
        acc.x += v.x * w; acc.y += v.y * w;
        acc.z += v.z * w; acc.w += v.w * w;
    }
    float inv = 1.f / L;
    *(float4*)&out[(size_t)row * HD + c4] =
        make_float4(acc.x * inv, acc.y * inv, acc.z * inv, acc.w * inv);
}

// ---------------------------------------------------------------------------
extern "C" void kernel_launch(void* const* d_in, const int* in_sizes, int n_in,
                              void* d_out, int out_size)
{
    const float* x  = (const float*)d_in[0];
    const float* Wq = (const float*)d_in[1];
    const float* Wk = (const float*)d_in[2];
    const float* Wv = (const float*)d_in[3];
    const float* cs = (const float*)d_in[4];
    const float* sn = (const float*)d_in[5];
    float* out = (float*)d_out;

    cudaFuncSetAttribute(gemm_qk_kernel,
                         cudaFuncAttributeMaxDynamicSharedMemorySize, QK_SMEM);
    cudaFuncSetAttribute(gemm_v_kernel,
                         cudaFuncAttributeMaxDynamicSharedMemorySize, V_SMEM);
    cudaFuncSetAttribute(flash_kernel,
                         cudaFuncAttributeMaxDynamicSharedMemorySize, FLASH_SMEM);

    wsplit_kernel<<<(3*NW4 + 255)/256, 256>>>(Wq, Wk, Wv);
    gemm_qk_kernel<<<dim3(2, Mn/128), 256, QK_SMEM>>>(x, cs, sn);
    gemm_v_kernel<<<dim3(1, Mn/64), 256, V_SMEM>>>(x);
    flash_kernel<<<296, 128, FLASH_SMEM>>>();
    merge_kernel<<<(Mn*HD/4 + 255)/256, 256>>>(out);
}